// round 1
// baseline (speedup 1.0000x reference)
#include <cuda_runtime.h>
#include <math.h>

#define EPSV 1e-5f

#define BATCH 16
#define CLSN 20
#define CDIM 768
#define NHEADS 4
#define DHEAD 192
#define NP 1024
#define ROWS (BATCH*CLSN)            /* 320 */
#define PPB (CDIM*NP)                /* 786432 elems per batch of input_patch */
#define KPAD 192                     /* padded im2col K (180 -> 192) */

// ---------------- scratch (device globals; no allocations allowed) ----------
__device__ float g_xln[ROWS*CDIM];
__device__ float g_q[ROWS*CDIM];
__device__ float g_sums[32];                       // [0:16] sum, [16:32] sumsq per batch
__device__ float g_nx[BATCH*CDIM*NP];              // 50 MB
__device__ float g_kv[BATCH*2*CDIM*NP];            // 100 MB
__device__ float g_attn[BATCH*NHEADS*CLSN*NP];     // 5.2 MB
__device__ float g_outflat[ROWS*CDIM];
__device__ float g_opatch[BATCH*CLSN*NP];
__device__ float g_im2col[BATCH*KPAD*NP];          // 12.6 MB
__device__ float g_W2[CDIM*KPAD];
__device__ float g_alpha[CDIM];
__device__ float g_beta[CDIM];

__device__ __forceinline__ float gelu_exact(float x) {
    return 0.5f * x * (1.0f + erff(x * 0.70710678118654752440f));
}

// ---------------- zero init for atomics ------------------------------------
__global__ void k_zero() {
    int i = blockIdx.x * 256 + threadIdx.x;
    if (i < ROWS*CDIM) g_outflat[i] = 0.0f;
    if (i < 32) g_sums[i] = 0.0f;
}

// ---------------- layernorm of x_cls rows (320 rows of 768) ----------------
__global__ void k_lncls(const float* __restrict__ x, const float* __restrict__ w,
                        const float* __restrict__ bb) {
    int r = blockIdx.x, tid = threadIdx.x;
    const float* xr = x + r * CDIM;
    float v0 = xr[tid], v1 = xr[tid+256], v2 = xr[tid+512];
    __shared__ float red[256];
    __shared__ float s_mu, s_rs;
    red[tid] = v0 + v1 + v2; __syncthreads();
    for (int o = 128; o; o >>= 1) { if (tid < o) red[tid] += red[tid+o]; __syncthreads(); }
    if (tid == 0) s_mu = red[0] * (1.0f/768.0f);
    __syncthreads();
    float mu = s_mu;
    float d0 = v0-mu, d1 = v1-mu, d2 = v2-mu;
    red[tid] = d0*d0 + d1*d1 + d2*d2; __syncthreads();
    for (int o = 128; o; o >>= 1) { if (tid < o) red[tid] += red[tid+o]; __syncthreads(); }
    if (tid == 0) s_rs = rsqrtf(red[0] * (1.0f/768.0f) + EPSV);
    __syncthreads();
    float rs = s_rs;
    float* o = g_xln + r * CDIM;
    o[tid]     = d0*rs*w[tid]     + bb[tid];
    o[tid+256] = d1*rs*w[tid+256] + bb[tid+256];
    o[tid+512] = d2*rs*w[tid+512] + bb[tid+512];
}

// ---------------- per-batch sums over input_patch ---------------------------
__global__ void k_psum(const float* __restrict__ x) {
    int b = blockIdx.y, tid = threadIdx.x;
    const float* p = x + (size_t)b * PPB + blockIdx.x * 16384 + tid;
    float s = 0.0f, q = 0.0f;
    #pragma unroll 8
    for (int i = 0; i < 64; i++) { float v = p[i*256]; s += v; q += v*v; }
    __shared__ float rs[256], rq[256];
    rs[tid] = s; rq[tid] = q; __syncthreads();
    for (int o = 128; o; o >>= 1) {
        if (tid < o) { rs[tid] += rs[tid+o]; rq[tid] += rq[tid+o]; }
        __syncthreads();
    }
    if (tid == 0) { atomicAdd(&g_sums[b], rs[0]); atomicAdd(&g_sums[16+b], rq[0]); }
}

// ---------------- normalize input_patch -> g_nx -----------------------------
__global__ void k_nx(const float* __restrict__ x, const float* __restrict__ w,
                     const float* __restrict__ bb) {
    int i = blockIdx.x * 256 + threadIdx.x;
    int b = i / PPB;
    int c = (i - b * PPB) >> 10;
    float mu  = g_sums[b]    * (1.0f/786432.0f);
    float var = g_sums[16+b] * (1.0f/786432.0f) - mu*mu;
    float r = rsqrtf(var + EPSV);
    g_nx[i] = (x[i] - mu) * r * w[c] + bb[c];
}

// ---------------- NT GEMM 64x64: C[320,768] = A[320,768] @ Bw[768,768]^T ----
// MODE 0: A=g_xln, C=g_q, +bias      MODE 1: A=g_outflat, C=Cext, +bias+res
template<int MODE>
__global__ void __launch_bounds__(256) gemm_nt(const float* __restrict__ Bw,
                                               const float* __restrict__ bias,
                                               const float* __restrict__ res,
                                               float* __restrict__ Cext) {
    const float* A = (MODE == 0) ? g_xln : g_outflat;
    float* C = (MODE == 0) ? g_q : Cext;
    __shared__ float As[16*68];
    __shared__ float Bs[16*68];
    int m0 = blockIdx.y * 64, n0 = blockIdx.x * 64;
    int tid = threadIdx.x, tx = tid & 15, ty = tid >> 4;
    float acc[4][4] = {};
    int row = tid >> 2, kq = tid & 3;
    for (int k0 = 0; k0 < 768; k0 += 16) {
        float4 va = *(const float4*)(A  + (m0+row)*768 + k0 + kq*4);
        float4 vb = *(const float4*)(Bw + (n0+row)*768 + k0 + kq*4);
        As[(kq*4+0)*68+row] = va.x; As[(kq*4+1)*68+row] = va.y;
        As[(kq*4+2)*68+row] = va.z; As[(kq*4+3)*68+row] = va.w;
        Bs[(kq*4+0)*68+row] = vb.x; Bs[(kq*4+1)*68+row] = vb.y;
        Bs[(kq*4+2)*68+row] = vb.z; Bs[(kq*4+3)*68+row] = vb.w;
        __syncthreads();
        #pragma unroll
        for (int k = 0; k < 16; k++) {
            float4 a4 = *(const float4*)(&As[k*68 + ty*4]);
            float4 b4 = *(const float4*)(&Bs[k*68 + tx*4]);
            float am[4] = {a4.x, a4.y, a4.z, a4.w};
            float bn[4] = {b4.x, b4.y, b4.z, b4.w};
            #pragma unroll
            for (int i = 0; i < 4; i++)
                #pragma unroll
                for (int j = 0; j < 4; j++) acc[i][j] += am[i]*bn[j];
        }
        __syncthreads();
    }
    #pragma unroll
    for (int i = 0; i < 4; i++) {
        int m = m0 + ty*4 + i;
        #pragma unroll
        for (int j = 0; j < 4; j++) {
            int n = n0 + tx*4 + j;
            float v = acc[i][j] + bias[n];
            if (MODE == 1) v += res[m*768 + n];
            C[m*768 + n] = v;
        }
    }
}

// ---------------- big NN GEMM 128x64x16, batched, N=1024 fixed --------------
// MODE 0 (kv):   C[b][1536,1024] = Wkv[1536,768] @ g_nx[b][768,1024] + bias[m]
// MODE 1 (conv): C[b][768,1024]  = gelu( (g_W2[768,192] @ g_im2col[b]) * alpha[m] + beta[m] )
template<int MODE>
__global__ void __launch_bounds__(256) gemm_big(const float* __restrict__ Aarg,
                                                const float* __restrict__ bias,
                                                float* __restrict__ Cout) {
    const int K = (MODE == 0) ? 768 : KPAD;
    int b = blockIdx.z;
    const float* A = (MODE == 0) ? Aarg : g_W2;
    const float* Bm = (MODE == 0) ? (g_nx + (size_t)b * PPB)
                                  : (g_im2col + (size_t)b * KPAD * NP);
    float* C = (MODE == 0) ? (g_kv + (size_t)b * 2*CDIM*NP)
                           : (Cout + (size_t)b * CDIM*NP);
    __shared__ float As[16*132];
    __shared__ float Bs[16*64];
    int m0 = blockIdx.y * 128, n0 = blockIdx.x * 64;
    int tid = threadIdx.x, tx = tid & 15, ty = tid >> 4;
    float acc[8][4] = {};
    for (int k0 = 0; k0 < K; k0 += 16) {
        #pragma unroll
        for (int l = 0; l < 2; l++) {
            int f = tid + l*256;
            int row = f >> 2, kq = f & 3;
            float4 v = *(const float4*)(A + (m0+row)*K + k0 + kq*4);
            As[(kq*4+0)*132+row] = v.x; As[(kq*4+1)*132+row] = v.y;
            As[(kq*4+2)*132+row] = v.z; As[(kq*4+3)*132+row] = v.w;
        }
        {
            int krow = tid >> 4, nq = tid & 15;
            float4 v = *(const float4*)(Bm + (k0+krow)*NP + n0 + nq*4);
            *(float4*)(&Bs[krow*64 + nq*4]) = v;
        }
        __syncthreads();
        #pragma unroll
        for (int k = 0; k < 16; k++) {
            float4 a0 = *(const float4*)(&As[k*132 + ty*8]);
            float4 a1 = *(const float4*)(&As[k*132 + ty*8 + 4]);
            float4 b4 = *(const float4*)(&Bs[k*64 + tx*4]);
            float am[8] = {a0.x,a0.y,a0.z,a0.w,a1.x,a1.y,a1.z,a1.w};
            float bn[4] = {b4.x,b4.y,b4.z,b4.w};
            #pragma unroll
            for (int i = 0; i < 8; i++)
                #pragma unroll
                for (int j = 0; j < 4; j++) acc[i][j] += am[i]*bn[j];
        }
        __syncthreads();
    }
    #pragma unroll
    for (int i = 0; i < 8; i++) {
        int m = m0 + ty*8 + i;
        float4 v;
        if (MODE == 0) {
            float be = bias[m];
            v = make_float4(acc[i][0]+be, acc[i][1]+be, acc[i][2]+be, acc[i][3]+be);
        } else {
            float al = g_alpha[m], be = g_beta[m];
            v = make_float4(gelu_exact(acc[i][0]*al+be), gelu_exact(acc[i][1]*al+be),
                            gelu_exact(acc[i][2]*al+be), gelu_exact(acc[i][3]*al+be));
        }
        *(float4*)(&C[m*NP + n0 + tx*4]) = v;
    }
}

// ---------------- attention logits: q @ key, scaled -------------------------
__global__ void __launch_bounds__(256) k_logits() {
    int chunk = blockIdx.x, h = blockIdx.y, b = blockIdx.z;
    int tid = threadIdx.x;
    __shared__ float qs[CLSN*DHEAD];
    for (int i = tid; i < CLSN*DHEAD; i += 256) {
        int m = i / DHEAD, d = i - m*DHEAD;
        qs[i] = g_q[(b*CLSN + m)*CDIM + h*DHEAD + d];
    }
    __syncthreads();
    int n = chunk*256 + tid;
    const float* kvp = g_kv + (size_t)b * 2*CDIM*NP + (size_t)(h*DHEAD) * NP + n;
    float acc[CLSN] = {};
    for (int d = 0; d < DHEAD; d++) {
        float kval = kvp[(size_t)d * NP];
        #pragma unroll
        for (int m = 0; m < CLSN; m++) acc[m] += qs[m*DHEAD + d] * kval;
    }
    const float scale = 0.07216878364870322f;  // 1/sqrt(192)
    float* ap = g_attn + (((size_t)(b*NHEADS + h))*CLSN)*NP + n;
    #pragma unroll
    for (int m = 0; m < CLSN; m++) ap[(size_t)m*NP] = acc[m] * scale;
}

// ---------------- softmax over rows of 1024 ---------------------------------
__global__ void k_softmax() {
    int row = blockIdx.x, tid = threadIdx.x;
    float* p = g_attn + (size_t)row * NP;
    float v[4];
    #pragma unroll
    for (int i = 0; i < 4; i++) v[i] = p[tid + i*256];
    float mx = fmaxf(fmaxf(v[0],v[1]), fmaxf(v[2],v[3]));
    __shared__ float red[256];
    red[tid] = mx; __syncthreads();
    for (int o = 128; o; o >>= 1) { if (tid < o) red[tid] = fmaxf(red[tid], red[tid+o]); __syncthreads(); }
    mx = red[0]; __syncthreads();
    float s = 0.0f;
    #pragma unroll
    for (int i = 0; i < 4; i++) { v[i] = expf(v[i] - mx); s += v[i]; }
    red[tid] = s; __syncthreads();
    for (int o = 128; o; o >>= 1) { if (tid < o) red[tid] += red[tid+o]; __syncthreads(); }
    float inv = 1.0f / red[0];
    #pragma unroll
    for (int i = 0; i < 4; i++) p[tid + i*256] = v[i] * inv;
}

// ---------------- out = attn @ val  (accumulate via atomics) ----------------
__global__ void __launch_bounds__(192) k_out() {
    int chunk = blockIdx.x, h = blockIdx.y, b = blockIdx.z;
    int tid = threadIdx.x;           // d in [0,192)
    __shared__ float attn_s[CLSN*256];
    for (int i = tid; i < CLSN*256; i += 192) {
        int m = i >> 8, nn = i & 255;
        attn_s[i] = g_attn[(((size_t)(b*NHEADS + h))*CLSN + m)*NP + chunk*256 + nn];
    }
    __syncthreads();
    const float* vp = g_kv + (size_t)b * 2*CDIM*NP
                    + (size_t)(CDIM + h*DHEAD + tid) * NP + chunk*256;
    float acc[CLSN] = {};
    for (int nn = 0; nn < 256; nn++) {
        float vv = vp[nn];
        #pragma unroll
        for (int m = 0; m < CLSN; m++) acc[m] += attn_s[m*256 + nn] * vv;
    }
    #pragma unroll
    for (int m = 0; m < CLSN; m++)
        atomicAdd(&g_outflat[(b*CLSN + m)*CDIM + h*DHEAD + tid], acc[m]);
}

// ---------------- out_patch = out_cls @ input_patch -------------------------
__global__ void __launch_bounds__(256) k_opatch(const float* __restrict__ patch,
                                                const float* __restrict__ ocls) {
    int chunk = blockIdx.x, b = blockIdx.y;
    int tid = threadIdx.x;
    int n = chunk*256 + tid;
    __shared__ float a_s[CLSN*96];
    float acc[CLSN] = {};
    for (int k0 = 0; k0 < 768; k0 += 96) {
        __syncthreads();
        for (int i = tid; i < CLSN*96; i += 256) {
            int m = i / 96, kk = i - m*96;
            a_s[i] = ocls[(b*CLSN + m)*CDIM + k0 + kk];
        }
        __syncthreads();
        for (int kk = 0; kk < 96; kk++) {
            float pv = patch[(size_t)b*PPB + (size_t)(k0+kk)*NP + n];
            #pragma unroll
            for (int m = 0; m < CLSN; m++) acc[m] += a_s[m*96 + kk] * pv;
        }
    }
    #pragma unroll
    for (int m = 0; m < CLSN; m++) g_opatch[((size_t)b*CLSN + m)*NP + n] = acc[m];
}

// ---------------- conv weight pad + BN fold ---------------------------------
__global__ void k_prepconv(const float* __restrict__ Wc, const float* __restrict__ bc,
                           const float* __restrict__ g,  const float* __restrict__ bt,
                           const float* __restrict__ mn, const float* __restrict__ vr) {
    int i = blockIdx.x * 256 + threadIdx.x;
    if (i < CDIM*KPAD) {
        int o = i / KPAD, k = i - o*KPAD;
        g_W2[i] = (k < 180) ? Wc[o*180 + k] : 0.0f;
    }
    if (i < CDIM) {
        float al = g[i] * rsqrtf(vr[i] + EPSV);
        g_alpha[i] = al;
        g_beta[i]  = (bc[i] - mn[i]) * al + bt[i];
    }
}

// ---------------- im2col (3x3, pad 1) ---------------------------------------
__global__ void k_im2col() {
    int i = blockIdx.x * 256 + threadIdx.x;      // over 16*192*1024
    int b = i / (KPAD*NP);
    int rest = i - b * KPAD*NP;
    int r = rest >> 10;
    int p = rest & 1023;
    float val = 0.0f;
    if (r < 180) {
        int ic = r / 9, t = r - ic*9;
        int dh = t/3 - 1, dw = t%3 - 1;
        int hh = (p >> 5) + dh, ww = (p & 31) + dw;
        if (hh >= 0 && hh < 32 && ww >= 0 && ww < 32)
            val = g_opatch[((size_t)b*CLSN + ic)*NP + hh*32 + ww];
    }
    g_im2col[i] = val;
}

// ---------------- launcher ---------------------------------------------------
extern "C" void kernel_launch(void* const* d_in, const int* in_sizes, int n_in,
                              void* d_out, int out_size) {
    const float* x_cls  = (const float*)d_in[0];
    const float* patch  = (const float*)d_in[1];
    const float* ln_w   = (const float*)d_in[2];
    const float* ln_b   = (const float*)d_in[3];
    const float* nx_w   = (const float*)d_in[4];
    const float* nx_b   = (const float*)d_in[5];
    const float* Wq     = (const float*)d_in[6];
    const float* bq     = (const float*)d_in[7];
    const float* Wkv    = (const float*)d_in[8];
    const float* bkv    = (const float*)d_in[9];
    const float* Wp     = (const float*)d_in[10];
    const float* bp     = (const float*)d_in[11];
    const float* Wconv  = (const float*)d_in[12];
    const float* bconv  = (const float*)d_in[13];
    const float* bn_g   = (const float*)d_in[14];
    const float* bn_b   = (const float*)d_in[15];
    const float* bn_m   = (const float*)d_in[16];
    const float* bn_v   = (const float*)d_in[17];
    float* out_cls = (float*)d_out;              // [320,768]
    float* y       = out_cls + ROWS*CDIM;        // [16,768,1024]

    k_zero<<<(ROWS*CDIM + 255)/256, 256>>>();
    k_lncls<<<ROWS, 256>>>(x_cls, ln_w, ln_b);
    k_psum<<<dim3(48, BATCH), 256>>>(patch);
    k_nx<<<(BATCH*PPB)/256, 256>>>(patch, nx_w, nx_b);
    gemm_nt<0><<<dim3(12, 5), 256>>>(Wq, bq, nullptr, nullptr);
    gemm_big<0><<<dim3(16, 12, BATCH), 256>>>(Wkv, bkv, nullptr);
    k_logits<<<dim3(4, NHEADS, BATCH), 256>>>();
    k_softmax<<<BATCH*NHEADS*CLSN, 256>>>();
    k_out<<<dim3(4, NHEADS, BATCH), 192>>>();
    gemm_nt<1><<<dim3(12, 5), 256>>>(Wp, bp, x_cls, out_cls);
    k_prepconv<<<(CDIM*KPAD + 255)/256, 256>>>(Wconv, bconv, bn_g, bn_b, bn_m, bn_v);
    k_opatch<<<dim3(4, BATCH), 256>>>(patch, out_cls);
    k_im2col<<<(BATCH*KPAD*NP)/256, 256>>>();
    gemm_big<1><<<dim3(16, 6, BATCH), 256>>>(nullptr, nullptr, y);
}

// round 3
// speedup vs baseline: 1.4174x; 1.4174x over previous
#include <cuda_runtime.h>
#include <cuda_bf16.h>
#include <cstdint>
#include <math.h>

#define EPSV 1e-5f
#define BATCH 16
#define CLSN 20
#define CDIM 768
#define NHEADS 4
#define DHEAD 192
#define NP 1024
#define ROWS (BATCH*CLSN)
#define PPB (CDIM*NP)
#define KPAD 192

// ---------------- scratch ----------------------------------------------------
__device__ float g_xln[ROWS*CDIM];
__device__ float g_q[ROWS*CDIM];
__device__ float g_sums[32];
__device__ float g_kv[BATCH*2*CDIM*NP];
__device__ float g_attn[BATCH*NHEADS*CLSN*NP];
__device__ float g_outflat[ROWS*CDIM];
__device__ float g_opatch[BATCH*CLSN*NP];
__device__ float g_alpha[CDIM];
__device__ float g_beta[CDIM];
__device__ __align__(128) __nv_bfloat16 g_Wkvh[2*CDIM*CDIM];
__device__ __align__(128) __nv_bfloat16 g_Wkvl[2*CDIM*CDIM];
__device__ __align__(128) __nv_bfloat16 g_nxTh[BATCH*NP*CDIM];   // [b][n][c]
__device__ __align__(128) __nv_bfloat16 g_nxTl[BATCH*NP*CDIM];
__device__ __align__(128) __nv_bfloat16 g_W2h[CDIM*KPAD];
__device__ __align__(128) __nv_bfloat16 g_W2l[CDIM*KPAD];
__device__ __align__(128) __nv_bfloat16 g_ich[BATCH*NP*KPAD];    // [b][n][k]
__device__ __align__(128) __nv_bfloat16 g_icl[BATCH*NP*KPAD];

__device__ __forceinline__ float gelu_exact(float x) {
    return 0.5f * x * (1.0f + erff(x * 0.70710678118654752440f));
}
__device__ __forceinline__ uint32_t s2u(const void* p) {
    uint32_t a;
    asm("{ .reg .u64 t; cvta.to.shared.u64 t, %1; cvt.u32.u64 %0, t; }" : "=r"(a) : "l"(p));
    return a;
}
__device__ __forceinline__ void cp16(uint32_t dst, const void* src) {
    asm volatile("cp.async.cg.shared.global [%0], [%1], 16;" :: "r"(dst), "l"(src));
}
#define CP_COMMIT() asm volatile("cp.async.commit_group;" ::: "memory")
#define LDSM_X4(r0,r1,r2,r3,a) \
    asm volatile("ldmatrix.sync.aligned.m8n8.x4.shared.b16 {%0,%1,%2,%3}, [%4];" \
                 : "=r"(r0), "=r"(r1), "=r"(r2), "=r"(r3) : "r"(a))
#define MMA16816(c, a, b0, b1) \
    asm volatile("mma.sync.aligned.m16n8k16.row.col.f32.bf16.bf16.f32 " \
                 "{%0,%1,%2,%3}, {%4,%5,%6,%7}, {%8,%9}, {%0,%1,%2,%3};" \
                 : "+f"((c)[0]), "+f"((c)[1]), "+f"((c)[2]), "+f"((c)[3]) \
                 : "r"((a)[0]), "r"((a)[1]), "r"((a)[2]), "r"((a)[3]), "r"(b0), "r"(b1))

// ---------------- small kernels ---------------------------------------------
__global__ void k_zero() {
    int i = blockIdx.x * 256 + threadIdx.x;
    if (i < ROWS*CDIM) g_outflat[i] = 0.0f;
    if (i < 32) g_sums[i] = 0.0f;
}

__global__ void k_lncls(const float* __restrict__ x, const float* __restrict__ w,
                        const float* __restrict__ bb) {
    int r = blockIdx.x, tid = threadIdx.x;
    const float* xr = x + r * CDIM;
    float v0 = xr[tid], v1 = xr[tid+256], v2 = xr[tid+512];
    __shared__ float red[256];
    __shared__ float s_mu, s_rs;
    red[tid] = v0 + v1 + v2; __syncthreads();
    for (int o = 128; o; o >>= 1) { if (tid < o) red[tid] += red[tid+o]; __syncthreads(); }
    if (tid == 0) s_mu = red[0] * (1.0f/768.0f);
    __syncthreads();
    float mu = s_mu;
    float d0 = v0-mu, d1 = v1-mu, d2 = v2-mu;
    red[tid] = d0*d0 + d1*d1 + d2*d2; __syncthreads();
    for (int o = 128; o; o >>= 1) { if (tid < o) red[tid] += red[tid+o]; __syncthreads(); }
    if (tid == 0) s_rs = rsqrtf(red[0] * (1.0f/768.0f) + EPSV);
    __syncthreads();
    float rs = s_rs;
    float* o = g_xln + r * CDIM;
    o[tid]     = d0*rs*w[tid]     + bb[tid];
    o[tid+256] = d1*rs*w[tid+256] + bb[tid+256];
    o[tid+512] = d2*rs*w[tid+512] + bb[tid+512];
}

__global__ void k_psum(const float* __restrict__ x) {
    int b = blockIdx.y, tid = threadIdx.x;
    const float* p = x + (size_t)b * PPB + blockIdx.x * 16384 + tid;
    float s = 0.0f, q = 0.0f;
    #pragma unroll 8
    for (int i = 0; i < 64; i++) { float v = p[i*256]; s += v; q += v*v; }
    __shared__ float rs[256], rq[256];
    rs[tid] = s; rq[tid] = q; __syncthreads();
    for (int o = 128; o; o >>= 1) {
        if (tid < o) { rs[tid] += rs[tid+o]; rq[tid] += rq[tid+o]; }
        __syncthreads();
    }
    if (tid == 0) { atomicAdd(&g_sums[b], rs[0]); atomicAdd(&g_sums[16+b], rq[0]); }
}

// normalize + transpose + bf16 hi/lo split:  g_nxT*[b][n][c]
__global__ void __launch_bounds__(256) k_nxT(const float* __restrict__ x,
                                             const float* __restrict__ w,
                                             const float* __restrict__ bb) {
    __shared__ float t[32][33];
    int b = blockIdx.z, c0 = blockIdx.y*32, n0 = blockIdx.x*32;
    int tx = threadIdx.x & 31, ty = threadIdx.x >> 5;
    float mu  = g_sums[b]    * (1.0f/786432.0f);
    float var = g_sums[16+b] * (1.0f/786432.0f) - mu*mu;
    float rv = rsqrtf(var + EPSV);
    #pragma unroll
    for (int i = 0; i < 4; i++) {
        int c = c0 + ty + i*8;
        float v = x[(size_t)b*PPB + (size_t)c*NP + n0 + tx];
        t[tx][ty + i*8] = (v - mu)*rv*w[c] + bb[c];
    }
    __syncthreads();
    #pragma unroll
    for (int i = 0; i < 4; i++) {
        int n = n0 + ty + i*8;
        float v = t[ty + i*8][tx];
        __nv_bfloat16 h = __float2bfloat16(v);
        size_t o = ((size_t)b*NP + n)*CDIM + c0 + tx;
        g_nxTh[o] = h;
        g_nxTl[o] = __float2bfloat16(v - __bfloat162float(h));
    }
}

__global__ void k_prep_wkv(const float* __restrict__ W) {
    int i = blockIdx.x * 256 + threadIdx.x;
    if (i < 2*CDIM*CDIM) {
        float x = W[i];
        __nv_bfloat16 h = __float2bfloat16(x);
        g_Wkvh[i] = h;
        g_Wkvl[i] = __float2bfloat16(x - __bfloat162float(h));
    }
}

__global__ void k_prepconv(const float* __restrict__ Wc, const float* __restrict__ bc,
                           const float* __restrict__ g,  const float* __restrict__ bt,
                           const float* __restrict__ mn, const float* __restrict__ vr) {
    int i = blockIdx.x * 256 + threadIdx.x;
    if (i < CDIM*KPAD) {
        int o = i / KPAD, k = i - o*KPAD;
        float x = (k < 180) ? Wc[o*180 + k] : 0.0f;
        __nv_bfloat16 h = __float2bfloat16(x);
        g_W2h[i] = h;
        g_W2l[i] = __float2bfloat16(x - __bfloat162float(h));
    }
    if (i < CDIM) {
        float al = g[i] * rsqrtf(vr[i] + EPSV);
        g_alpha[i] = al;
        g_beta[i]  = (bc[i] - mn[i]) * al + bt[i];
    }
}

// ---------------- small NT GEMM (q proj / out proj) --------------------------
template<int MODE>
__global__ void __launch_bounds__(256) gemm_nt(const float* __restrict__ Bw,
                                               const float* __restrict__ bias,
                                               const float* __restrict__ res,
                                               float* __restrict__ Cext) {
    const float* A = (MODE == 0) ? g_xln : g_outflat;
    float* C = (MODE == 0) ? g_q : Cext;
    __shared__ float As[16*68];
    __shared__ float Bs[16*68];
    int m0 = blockIdx.y * 64, n0 = blockIdx.x * 64;
    int tid = threadIdx.x, tx = tid & 15, ty = tid >> 4;
    float acc[4][4] = {};
    int row = tid >> 2, kq = tid & 3;
    for (int k0 = 0; k0 < 768; k0 += 16) {
        float4 va = *(const float4*)(A  + (m0+row)*768 + k0 + kq*4);
        float4 vb = *(const float4*)(Bw + (n0+row)*768 + k0 + kq*4);
        As[(kq*4+0)*68+row] = va.x; As[(kq*4+1)*68+row] = va.y;
        As[(kq*4+2)*68+row] = va.z; As[(kq*4+3)*68+row] = va.w;
        Bs[(kq*4+0)*68+row] = vb.x; Bs[(kq*4+1)*68+row] = vb.y;
        Bs[(kq*4+2)*68+row] = vb.z; Bs[(kq*4+3)*68+row] = vb.w;
        __syncthreads();
        #pragma unroll
        for (int k = 0; k < 16; k++) {
            float4 a4 = *(const float4*)(&As[k*68 + ty*4]);
            float4 b4 = *(const float4*)(&Bs[k*68 + tx*4]);
            float am[4] = {a4.x, a4.y, a4.z, a4.w};
            float bn[4] = {b4.x, b4.y, b4.z, b4.w};
            #pragma unroll
            for (int i = 0; i < 4; i++)
                #pragma unroll
                for (int j = 0; j < 4; j++) acc[i][j] += am[i]*bn[j];
        }
        __syncthreads();
    }
    #pragma unroll
    for (int i = 0; i < 4; i++) {
        int m = m0 + ty*4 + i;
        #pragma unroll
        for (int j = 0; j < 4; j++) {
            int n = n0 + tx*4 + j;
            float v = acc[i][j] + bias[n];
            if (MODE == 1) v += res[m*768 + n];
            C[m*768 + n] = v;
        }
    }
}

// ---------------- mma.sync bf16-split GEMM (family-generic tensor cores) -----
// C[128,128] CTA tile.  C = Ah*Bh^T + Ah*Bl^T + Al*Bh^T, fp32 accum.
// A row-major [M][K] bf16 (K contig), B row-major [N][K] bf16 (K contig).
// MODE 0 (kv):   M=1536 K=768, B=nxT[b], C=g_kv[b], +bias[m]
// MODE 1 (conv): M=768  K=192, B=ic[b],  C=y[b],   gelu(alpha[m]*x+beta[m])
#define APITCH 80
#define ASIZE (128*APITCH)
#define STAGE (2*ASIZE)
template<int MODE>
__global__ void __launch_bounds__(256) gemm_mma(const float* __restrict__ bias,
                                                float* __restrict__ Cout) {
    const int K  = (MODE == 0) ? 768 : KPAD;
    const int KS = K / 32;
    const int NS = 3 * KS;
    __shared__ __align__(1024) char sm[2*STAGE];
    uint32_t sb = s2u(sm);
    int tid = threadIdx.x;
    int w = tid >> 5, l = tid & 31;
    int wm = w >> 1, wn = w & 1;
    int b = blockIdx.z;
    int m0 = blockIdx.y * 128, n0 = blockIdx.x * 128;

    const __nv_bfloat16* Ah = (MODE == 0) ? g_Wkvh : g_W2h;
    const __nv_bfloat16* Al = (MODE == 0) ? g_Wkvl : g_W2l;
    const __nv_bfloat16* Bh = ((MODE == 0) ? g_nxTh : g_ich) + (size_t)b * NP * K;
    const __nv_bfloat16* Bl = ((MODE == 0) ? g_nxTl : g_icl) + (size_t)b * NP * K;
    float* C = (MODE == 0) ? (g_kv + (size_t)b * 2*CDIM*NP)
                           : (Cout + (size_t)b * CDIM*NP);

    float acc[2][8][4] = {};

    // per-thread load indices: 2 chunks for A, 2 for B
    int c0i = tid, c1i = tid + 256;
    int r0 = c0i >> 2, q0 = c0i & 3;
    int r1 = c1i >> 2, q1 = c1i & 3;

    auto load_stage = [&](int st, int pass, int k0) {
        const __nv_bfloat16* Ap = (pass == 2) ? Al : Ah;
        const __nv_bfloat16* Bp = (pass == 1) ? Bl : Bh;
        uint32_t sa = sb + st*STAGE;
        uint32_t sbB = sa + ASIZE;
        cp16(sa  + r0*APITCH + q0*16, Ap + (size_t)(m0+r0)*K + k0 + q0*8);
        cp16(sa  + r1*APITCH + q1*16, Ap + (size_t)(m0+r1)*K + k0 + q1*8);
        cp16(sbB + r0*APITCH + q0*16, Bp + (size_t)(n0+r0)*K + k0 + q0*8);
        cp16(sbB + r1*APITCH + q1*16, Bp + (size_t)(n0+r1)*K + k0 + q1*8);
    };

    load_stage(0, 0, 0);
    CP_COMMIT();

    int lrow = (l & 7) + ((l >> 3) & 1) * 8;   // row within 16-row tile
    int lk   = (l >> 4) * 8;                   // k-offset within 16

    for (int s = 0; s < NS; s++) {
        if (s + 1 < NS) {
            int nx = s + 1;
            load_stage(nx & 1, nx / KS, (nx % KS) * 32);
            CP_COMMIT();
            asm volatile("cp.async.wait_group 1;" ::: "memory");
        } else {
            asm volatile("cp.async.wait_group 0;" ::: "memory");
        }
        __syncthreads();
        uint32_t abase = sb + (s & 1)*STAGE;
        uint32_t bbase = abase + ASIZE;
        #pragma unroll
        for (int kk = 0; kk < 2; kk++) {
            uint32_t a[2][4];
            #pragma unroll
            for (int mi = 0; mi < 2; mi++) {
                uint32_t ad = abase + (wm*32 + mi*16 + lrow)*APITCH + (kk*16 + lk)*2;
                LDSM_X4(a[mi][0], a[mi][1], a[mi][2], a[mi][3], ad);
            }
            uint32_t bf[4][4];
            #pragma unroll
            for (int np = 0; np < 4; np++) {
                uint32_t bd = bbase + (wn*64 + np*16 + lrow)*APITCH + (kk*16 + lk)*2;
                LDSM_X4(bf[np][0], bf[np][1], bf[np][2], bf[np][3], bd);
            }
            #pragma unroll
            for (int mi = 0; mi < 2; mi++)
                #pragma unroll
                for (int ni = 0; ni < 8; ni++) {
                    int np = ni >> 1;
                    uint32_t b0 = (ni & 1) ? bf[np][1] : bf[np][0];
                    uint32_t b1 = (ni & 1) ? bf[np][3] : bf[np][2];
                    MMA16816(acc[mi][ni], a[mi], b0, b1);
                }
        }
        __syncthreads();
    }

    // epilogue
    #pragma unroll
    for (int mi = 0; mi < 2; mi++) {
        int rA = m0 + wm*32 + mi*16 + (l >> 2);
        int rB = rA + 8;
        float pA0, pA1, pB0, pB1;
        if (MODE == 0) { pA0 = bias[rA]; pA1 = 0.0f; pB0 = bias[rB]; pB1 = 0.0f; }
        else { pA0 = g_alpha[rA]; pA1 = g_beta[rA]; pB0 = g_alpha[rB]; pB1 = g_beta[rB]; }
        #pragma unroll
        for (int ni = 0; ni < 8; ni++) {
            int col = n0 + wn*64 + ni*8 + (l & 3)*2;
            float* c = acc[mi][ni];
            float2 vA, vB;
            if (MODE == 0) {
                vA = make_float2(c[0] + pA0, c[1] + pA0);
                vB = make_float2(c[2] + pB0, c[3] + pB0);
            } else {
                vA = make_float2(gelu_exact(c[0]*pA0 + pA1), gelu_exact(c[1]*pA0 + pA1));
                vB = make_float2(gelu_exact(c[2]*pB0 + pB1), gelu_exact(c[3]*pB0 + pB1));
            }
            *(float2*)(C + (size_t)rA*NP + col) = vA;
            *(float2*)(C + (size_t)rB*NP + col) = vB;
        }
    }
}

// ---------------- attention -------------------------------------------------
__global__ void __launch_bounds__(256) k_logits() {
    int chunk = blockIdx.x, h = blockIdx.y, b = blockIdx.z;
    int tid = threadIdx.x;
    __shared__ float qs[CLSN*DHEAD];
    for (int i = tid; i < CLSN*DHEAD; i += 256) {
        int m = i / DHEAD, d = i - m*DHEAD;
        qs[i] = g_q[(b*CLSN + m)*CDIM + h*DHEAD + d];
    }
    __syncthreads();
    int n = chunk*256 + tid;
    const float* kvp = g_kv + (size_t)b * 2*CDIM*NP + (size_t)(h*DHEAD) * NP + n;
    float acc[CLSN] = {};
    for (int d = 0; d < DHEAD; d++) {
        float kval = kvp[(size_t)d * NP];
        #pragma unroll
        for (int m = 0; m < CLSN; m++) acc[m] += qs[m*DHEAD + d] * kval;
    }
    const float scale = 0.07216878364870322f;
    float* ap = g_attn + (((size_t)(b*NHEADS + h))*CLSN)*NP + n;
    #pragma unroll
    for (int m = 0; m < CLSN; m++) ap[(size_t)m*NP] = acc[m] * scale;
}

__global__ void k_softmax() {
    int row = blockIdx.x, tid = threadIdx.x;
    float* p = g_attn + (size_t)row * NP;
    float v[4];
    #pragma unroll
    for (int i = 0; i < 4; i++) v[i] = p[tid + i*256];
    float mx = fmaxf(fmaxf(v[0],v[1]), fmaxf(v[2],v[3]));
    __shared__ float red[256];
    red[tid] = mx; __syncthreads();
    for (int o = 128; o; o >>= 1) { if (tid < o) red[tid] = fmaxf(red[tid], red[tid+o]); __syncthreads(); }
    mx = red[0]; __syncthreads();
    float s = 0.0f;
    #pragma unroll
    for (int i = 0; i < 4; i++) { v[i] = expf(v[i] - mx); s += v[i]; }
    red[tid] = s; __syncthreads();
    for (int o = 128; o; o >>= 1) { if (tid < o) red[tid] += red[tid+o]; __syncthreads(); }
    float inv = 1.0f / red[0];
    #pragma unroll
    for (int i = 0; i < 4; i++) p[tid + i*256] = v[i] * inv;
}

__global__ void __launch_bounds__(192) k_out() {
    int chunk = blockIdx.x, h = blockIdx.y, b = blockIdx.z;
    int tid = threadIdx.x;
    __shared__ float attn_s[CLSN*256];
    for (int i = tid; i < CLSN*256; i += 192) {
        int m = i >> 8, nn = i & 255;
        attn_s[i] = g_attn[(((size_t)(b*NHEADS + h))*CLSN + m)*NP + chunk*256 + nn];
    }
    __syncthreads();
    const float* vp = g_kv + (size_t)b * 2*CDIM*NP
                    + (size_t)(CDIM + h*DHEAD + tid) * NP + chunk*256;
    float acc[CLSN] = {};
    for (int nn = 0; nn < 256; nn++) {
        float vv = vp[nn];
        #pragma unroll
        for (int m = 0; m < CLSN; m++) acc[m] += attn_s[m*256 + nn] * vv;
    }
    #pragma unroll
    for (int m = 0; m < CLSN; m++)
        atomicAdd(&g_outflat[(b*CLSN + m)*CDIM + h*DHEAD + tid], acc[m]);
}

// ---------------- out_patch = out_cls @ input_patch --------------------------
__global__ void __launch_bounds__(256) k_opatch(const float* __restrict__ patch,
                                                const float* __restrict__ ocls) {
    int chunk = blockIdx.x, b = blockIdx.y;
    int tid = threadIdx.x;
    int n = chunk*256 + tid;
    __shared__ float a_s[CLSN*96];
    float acc[CLSN] = {};
    for (int k0 = 0; k0 < 768; k0 += 96) {
        __syncthreads();
        for (int i = tid; i < CLSN*96; i += 256) {
            int m = i / 96, kk = i - m*96;
            a_s[i] = ocls[(b*CLSN + m)*CDIM + k0 + kk];
        }
        __syncthreads();
        for (int kk = 0; kk < 96; kk++) {
            float pv = patch[(size_t)b*PPB + (size_t)(k0+kk)*NP + n];
            #pragma unroll
            for (int m = 0; m < CLSN; m++) acc[m] += a_s[m*96 + kk] * pv;
        }
    }
    #pragma unroll
    for (int m = 0; m < CLSN; m++) g_opatch[((size_t)b*CLSN + m)*NP + n] = acc[m];
}

// ---------------- im2col transposed + bf16 split -----------------------------
__global__ void k_im2colT() {
    int i = blockIdx.x * 256 + threadIdx.x;       // 16*1024*192
    int b = i / (NP*KPAD);
    int rest = i - b * NP*KPAD;
    int n = rest / KPAD, k = rest - n*KPAD;
    float val = 0.0f;
    if (k < 180) {
        int ic = k / 9, t = k - ic*9;
        int hh = (n >> 5) + t/3 - 1, ww = (n & 31) + t%3 - 1;
        if (hh >= 0 && hh < 32 && ww >= 0 && ww < 32)
            val = g_opatch[((size_t)b*CLSN + ic)*NP + hh*32 + ww];
    }
    __nv_bfloat16 h = __float2bfloat16(val);
    g_ich[i] = h;
    g_icl[i] = __float2bfloat16(val - __bfloat162float(h));
}

// ---------------- launcher ---------------------------------------------------
extern "C" void kernel_launch(void* const* d_in, const int* in_sizes, int n_in,
                              void* d_out, int out_size) {
    const float* x_cls  = (const float*)d_in[0];
    const float* patch  = (const float*)d_in[1];
    const float* ln_w   = (const float*)d_in[2];
    const float* ln_b   = (const float*)d_in[3];
    const float* nx_w   = (const float*)d_in[4];
    const float* nx_b   = (const float*)d_in[5];
    const float* Wq     = (const float*)d_in[6];
    const float* bq     = (const float*)d_in[7];
    const float* Wkv    = (const float*)d_in[8];
    const float* bkv    = (const float*)d_in[9];
    const float* Wp     = (const float*)d_in[10];
    const float* bp     = (const float*)d_in[11];
    const float* Wconv  = (const float*)d_in[12];
    const float* bconv  = (const float*)d_in[13];
    const float* bn_g   = (const float*)d_in[14];
    const float* bn_b   = (const float*)d_in[15];
    const float* bn_m   = (const float*)d_in[16];
    const float* bn_v   = (const float*)d_in[17];
    float* out_cls = (float*)d_out;
    float* y       = out_cls + ROWS*CDIM;

    k_zero<<<(ROWS*CDIM + 255)/256, 256>>>();
    k_lncls<<<ROWS, 256>>>(x_cls, ln_w, ln_b);
    k_psum<<<dim3(48, BATCH), 256>>>(patch);
    k_prep_wkv<<<(2*CDIM*CDIM)/256, 256>>>(Wkv);
    k_nxT<<<dim3(32, 24, BATCH), 256>>>(patch, nx_w, nx_b);
    gemm_nt<0><<<dim3(12, 5), 256>>>(Wq, bq, nullptr, nullptr);
    gemm_mma<0><<<dim3(8, 12, BATCH), 256>>>(bkv, nullptr);
    k_logits<<<dim3(4, NHEADS, BATCH), 256>>>();
    k_softmax<<<BATCH*NHEADS*CLSN, 256>>>();
    k_out<<<dim3(4, NHEADS, BATCH), 192>>>();
    gemm_nt<1><<<dim3(12, 5), 256>>>(Wp, bp, x_cls, out_cls);
    k_prepconv<<<(CDIM*KPAD + 255)/256, 256>>>(Wconv, bconv, bn_g, bn_b, bn_m, bn_v);
    k_opatch<<<dim3(4, BATCH), 256>>>(patch, out_cls);
    k_im2colT<<<(BATCH*NP*KPAD)/256, 256>>>();
    gemm_mma<1><<<dim3(8, 6, BATCH), 256>>>(nullptr, y);
}

// round 4
// speedup vs baseline: 1.4839x; 1.0469x over previous
#include <cuda_runtime.h>
#include <cuda_bf16.h>
#include <cstdint>
#include <math.h>

#define EPSV 1e-5f
#define BATCH 16
#define CLSN 20
#define CDIM 768
#define NHEADS 4
#define DHEAD 192
#define NP 1024
#define ROWS (BATCH*CLSN)
#define PPB (CDIM*NP)
#define KPAD 192

// ---------------- scratch ----------------------------------------------------
__device__ float g_xln[ROWS*CDIM];
__device__ float g_q[ROWS*CDIM];
__device__ float g_sums[32];
__device__ float g_kv[BATCH*2*CDIM*NP];
__device__ float g_attn[BATCH*NHEADS*CLSN*NP];
__device__ float g_outflat[ROWS*CDIM];
__device__ float g_opatch[BATCH*CLSN*NP];
__device__ float g_alpha[CDIM];
__device__ float g_beta[CDIM];
__device__ __align__(128) __nv_bfloat16 g_Wkvh[2*CDIM*CDIM];
__device__ __align__(128) __nv_bfloat16 g_Wkvl[2*CDIM*CDIM];
__device__ __align__(128) __nv_bfloat16 g_nxTh[BATCH*NP*CDIM];   // [b][n][c]
__device__ __align__(128) __nv_bfloat16 g_nxTl[BATCH*NP*CDIM];
__device__ __align__(128) __nv_bfloat16 g_W2h[CDIM*KPAD];
__device__ __align__(128) __nv_bfloat16 g_W2l[CDIM*KPAD];
__device__ __align__(128) __nv_bfloat16 g_ich[BATCH*NP*KPAD];    // [b][n][k]
__device__ __align__(128) __nv_bfloat16 g_icl[BATCH*NP*KPAD];

__device__ __forceinline__ float gelu_exact(float x) {
    return 0.5f * x * (1.0f + erff(x * 0.70710678118654752440f));
}
__device__ __forceinline__ uint32_t s2u(const void* p) {
    uint32_t a;
    asm("{ .reg .u64 t; cvta.to.shared.u64 t, %1; cvt.u32.u64 %0, t; }" : "=r"(a) : "l"(p));
    return a;
}
__device__ __forceinline__ void cp16(uint32_t dst, const void* src) {
    asm volatile("cp.async.cg.shared.global [%0], [%1], 16;" :: "r"(dst), "l"(src));
}
#define CP_COMMIT() asm volatile("cp.async.commit_group;" ::: "memory")
#define LDSM_X4(r0,r1,r2,r3,a) \
    asm volatile("ldmatrix.sync.aligned.m8n8.x4.shared.b16 {%0,%1,%2,%3}, [%4];" \
                 : "=r"(r0), "=r"(r1), "=r"(r2), "=r"(r3) : "r"(a))
#define MMA16816(c, a, b0, b1) \
    asm volatile("mma.sync.aligned.m16n8k16.row.col.f32.bf16.bf16.f32 " \
                 "{%0,%1,%2,%3}, {%4,%5,%6,%7}, {%8,%9}, {%0,%1,%2,%3};" \
                 : "+f"((c)[0]), "+f"((c)[1]), "+f"((c)[2]), "+f"((c)[3]) \
                 : "r"((a)[0]), "r"((a)[1]), "r"((a)[2]), "r"((a)[3]), "r"(b0), "r"(b1))

// ---------------- small kernels ---------------------------------------------
__global__ void k_zero() {
    int i = blockIdx.x * 256 + threadIdx.x;
    if (i < ROWS*CDIM) g_outflat[i] = 0.0f;
    if (i < 32) g_sums[i] = 0.0f;
}

__global__ void k_lncls(const float* __restrict__ x, const float* __restrict__ w,
                        const float* __restrict__ bb) {
    int r = blockIdx.x, tid = threadIdx.x;
    const float* xr = x + r * CDIM;
    float v0 = xr[tid], v1 = xr[tid+256], v2 = xr[tid+512];
    __shared__ float red[256];
    __shared__ float s_mu, s_rs;
    red[tid] = v0 + v1 + v2; __syncthreads();
    for (int o = 128; o; o >>= 1) { if (tid < o) red[tid] += red[tid+o]; __syncthreads(); }
    if (tid == 0) s_mu = red[0] * (1.0f/768.0f);
    __syncthreads();
    float mu = s_mu;
    float d0 = v0-mu, d1 = v1-mu, d2 = v2-mu;
    red[tid] = d0*d0 + d1*d1 + d2*d2; __syncthreads();
    for (int o = 128; o; o >>= 1) { if (tid < o) red[tid] += red[tid+o]; __syncthreads(); }
    if (tid == 0) s_rs = rsqrtf(red[0] * (1.0f/768.0f) + EPSV);
    __syncthreads();
    float rs = s_rs;
    float* o = g_xln + r * CDIM;
    o[tid]     = d0*rs*w[tid]     + bb[tid];
    o[tid+256] = d1*rs*w[tid+256] + bb[tid+256];
    o[tid+512] = d2*rs*w[tid+512] + bb[tid+512];
}

__global__ void k_psum(const float* __restrict__ x) {
    int b = blockIdx.y, tid = threadIdx.x;
    const float* p = x + (size_t)b * PPB + blockIdx.x * 16384 + tid;
    float s = 0.0f, q = 0.0f;
    #pragma unroll 8
    for (int i = 0; i < 64; i++) { float v = p[i*256]; s += v; q += v*v; }
    __shared__ float rs[256], rq[256];
    rs[tid] = s; rq[tid] = q; __syncthreads();
    for (int o = 128; o; o >>= 1) {
        if (tid < o) { rs[tid] += rs[tid+o]; rq[tid] += rq[tid+o]; }
        __syncthreads();
    }
    if (tid == 0) { atomicAdd(&g_sums[b], rs[0]); atomicAdd(&g_sums[16+b], rq[0]); }
}

// normalize + transpose + bf16 hi/lo split:  g_nxT*[b][n][c]
__global__ void __launch_bounds__(256) k_nxT(const float* __restrict__ x,
                                             const float* __restrict__ w,
                                             const float* __restrict__ bb) {
    __shared__ float t[32][33];
    int b = blockIdx.z, c0 = blockIdx.y*32, n0 = blockIdx.x*32;
    int tx = threadIdx.x & 31, ty = threadIdx.x >> 5;
    float mu  = g_sums[b]    * (1.0f/786432.0f);
    float var = g_sums[16+b] * (1.0f/786432.0f) - mu*mu;
    float rv = rsqrtf(var + EPSV);
    #pragma unroll
    for (int i = 0; i < 4; i++) {
        int c = c0 + ty + i*8;
        float v = x[(size_t)b*PPB + (size_t)c*NP + n0 + tx];
        t[tx][ty + i*8] = (v - mu)*rv*w[c] + bb[c];
    }
    __syncthreads();
    #pragma unroll
    for (int i = 0; i < 4; i++) {
        int n = n0 + ty + i*8;
        float v = t[ty + i*8][tx];
        __nv_bfloat16 h = __float2bfloat16(v);
        size_t o = ((size_t)b*NP + n)*CDIM + c0 + tx;
        g_nxTh[o] = h;
        g_nxTl[o] = __float2bfloat16(v - __bfloat162float(h));
    }
}

__global__ void k_prep_wkv(const float* __restrict__ W) {
    int i = blockIdx.x * 256 + threadIdx.x;
    if (i < 2*CDIM*CDIM) {
        float x = W[i];
        __nv_bfloat16 h = __float2bfloat16(x);
        g_Wkvh[i] = h;
        g_Wkvl[i] = __float2bfloat16(x - __bfloat162float(h));
    }
}

__global__ void k_prepconv(const float* __restrict__ Wc, const float* __restrict__ bc,
                           const float* __restrict__ g,  const float* __restrict__ bt,
                           const float* __restrict__ mn, const float* __restrict__ vr) {
    int i = blockIdx.x * 256 + threadIdx.x;
    if (i < CDIM*KPAD) {
        int o = i / KPAD, k = i - o*KPAD;
        float x = (k < 180) ? Wc[o*180 + k] : 0.0f;
        __nv_bfloat16 h = __float2bfloat16(x);
        g_W2h[i] = h;
        g_W2l[i] = __float2bfloat16(x - __bfloat162float(h));
    }
    if (i < CDIM) {
        float al = g[i] * rsqrtf(vr[i] + EPSV);
        g_alpha[i] = al;
        g_beta[i]  = (bc[i] - mn[i]) * al + bt[i];
    }
}

// ---------------- small NT GEMM (q proj / out proj) --------------------------
template<int MODE>
__global__ void __launch_bounds__(256) gemm_nt(const float* __restrict__ Bw,
                                               const float* __restrict__ bias,
                                               const float* __restrict__ res,
                                               float* __restrict__ Cext) {
    const float* A = (MODE == 0) ? g_xln : g_outflat;
    float* C = (MODE == 0) ? g_q : Cext;
    __shared__ float As[16*68];
    __shared__ float Bs[16*68];
    int m0 = blockIdx.y * 64, n0 = blockIdx.x * 64;
    int tid = threadIdx.x, tx = tid & 15, ty = tid >> 4;
    float acc[4][4] = {};
    int row = tid >> 2, kq = tid & 3;
    for (int k0 = 0; k0 < 768; k0 += 16) {
        float4 va = *(const float4*)(A  + (m0+row)*768 + k0 + kq*4);
        float4 vb = *(const float4*)(Bw + (n0+row)*768 + k0 + kq*4);
        As[(kq*4+0)*68+row] = va.x; As[(kq*4+1)*68+row] = va.y;
        As[(kq*4+2)*68+row] = va.z; As[(kq*4+3)*68+row] = va.w;
        Bs[(kq*4+0)*68+row] = vb.x; Bs[(kq*4+1)*68+row] = vb.y;
        Bs[(kq*4+2)*68+row] = vb.z; Bs[(kq*4+3)*68+row] = vb.w;
        __syncthreads();
        #pragma unroll
        for (int k = 0; k < 16; k++) {
            float4 a4 = *(const float4*)(&As[k*68 + ty*4]);
            float4 b4 = *(const float4*)(&Bs[k*68 + tx*4]);
            float am[4] = {a4.x, a4.y, a4.z, a4.w};
            float bn[4] = {b4.x, b4.y, b4.z, b4.w};
            #pragma unroll
            for (int i = 0; i < 4; i++)
                #pragma unroll
                for (int j = 0; j < 4; j++) acc[i][j] += am[i]*bn[j];
        }
        __syncthreads();
    }
    #pragma unroll
    for (int i = 0; i < 4; i++) {
        int m = m0 + ty*4 + i;
        #pragma unroll
        for (int j = 0; j < 4; j++) {
            int n = n0 + tx*4 + j;
            float v = acc[i][j] + bias[n];
            if (MODE == 1) v += res[m*768 + n];
            C[m*768 + n] = v;
        }
    }
}

// ---------------- mma.sync bf16-split GEMM, single-residency 3-pass ----------
// C[128,128] CTA tile. Per k16 slab load Ah/Al/Bh/Bl once, run all 3 passes.
// 3-stage cp.async pipeline in dynamic smem.
#define TPITCH 48                    /* bytes per k16 row: 32B data + 16B pad */
#define TBYTES (128*TPITCH)          /* 6144 per tile array */
#define STAGEB (4*TBYTES)            /* 24576: AH AL BH BL */
#define NSTG 3
#define SMEMB (NSTG*STAGEB)          /* 73728 */
template<int MODE>
__global__ void __launch_bounds__(256, 2) gemm_mma(const float* __restrict__ bias,
                                                   float* __restrict__ Cout) {
    const int K  = (MODE == 0) ? 768 : KPAD;
    const int NS = K / 16;
    extern __shared__ __align__(1024) char sm[];
    uint32_t sb = s2u(sm);
    int tid = threadIdx.x;
    int w = tid >> 5, l = tid & 31;
    int wm = w >> 1, wn = w & 1;
    int b = blockIdx.z;
    int m0 = blockIdx.y * 128, n0 = blockIdx.x * 128;

    const __nv_bfloat16* Ah = (MODE == 0) ? g_Wkvh : g_W2h;
    const __nv_bfloat16* Al = (MODE == 0) ? g_Wkvl : g_W2l;
    const __nv_bfloat16* Bh = ((MODE == 0) ? g_nxTh : g_ich) + (size_t)b * NP * K;
    const __nv_bfloat16* Bl = ((MODE == 0) ? g_nxTl : g_icl) + (size_t)b * NP * K;
    float* C = (MODE == 0) ? (g_kv + (size_t)b * 2*CDIM*NP)
                           : (Cout + (size_t)b * CDIM*NP);

    float acc[2][8][4] = {};

    int r = tid >> 1, q = tid & 1;           // row 0..127, 16B segment 0..1
    uint32_t so = r*TPITCH + q*16;
    size_t arow = (size_t)(m0 + r) * K + q*8;
    size_t brow = (size_t)(n0 + r) * K + q*8;

    auto load_stage = [&](int s) {
        uint32_t st = sb + (s % NSTG) * STAGEB;
        int k0 = s * 16;
        cp16(st + so,            Ah + arow + k0);
        cp16(st + TBYTES + so,   Al + arow + k0);
        cp16(st + 2*TBYTES + so, Bh + brow + k0);
        cp16(st + 3*TBYTES + so, Bl + brow + k0);
        CP_COMMIT();
    };
    load_stage(0);
    load_stage(1);

    int lrow = (l & 7) + ((l >> 3) & 1) * 8;
    int lko  = (l >> 4) * 16;                 // byte offset of k-half

    for (int s = 0; s < NS; s++) {
        if (s + 1 < NS) asm volatile("cp.async.wait_group 1;" ::: "memory");
        else            asm volatile("cp.async.wait_group 0;" ::: "memory");
        __syncthreads();
        if (s + 2 < NS) load_stage(s + 2);
        uint32_t st = sb + (s % NSTG) * STAGEB;
        uint32_t aro = st + (wm*32 + lrow)*TPITCH + lko;
        uint32_t bro = st + 2*TBYTES + (wn*64 + lrow)*TPITCH + lko;
        uint32_t ah[2][4], al[2][4], bf[4][4];
        #pragma unroll
        for (int mi = 0; mi < 2; mi++) {
            LDSM_X4(ah[mi][0], ah[mi][1], ah[mi][2], ah[mi][3], aro + mi*16*TPITCH);
            LDSM_X4(al[mi][0], al[mi][1], al[mi][2], al[mi][3], aro + TBYTES + mi*16*TPITCH);
        }
        #pragma unroll
        for (int np = 0; np < 4; np++)
            LDSM_X4(bf[np][0], bf[np][1], bf[np][2], bf[np][3], bro + np*16*TPITCH);
        #pragma unroll
        for (int mi = 0; mi < 2; mi++)
            #pragma unroll
            for (int ni = 0; ni < 8; ni++) {
                int np = ni >> 1;
                uint32_t b0 = (ni & 1) ? bf[np][1] : bf[np][0];
                uint32_t b1 = (ni & 1) ? bf[np][3] : bf[np][2];
                MMA16816(acc[mi][ni], ah[mi], b0, b1);
                MMA16816(acc[mi][ni], al[mi], b0, b1);
            }
        // B-lo pass, reuse bf regs
        #pragma unroll
        for (int np = 0; np < 4; np++)
            LDSM_X4(bf[np][0], bf[np][1], bf[np][2], bf[np][3], bro + TBYTES + np*16*TPITCH);
        #pragma unroll
        for (int mi = 0; mi < 2; mi++)
            #pragma unroll
            for (int ni = 0; ni < 8; ni++) {
                int np = ni >> 1;
                uint32_t b0 = (ni & 1) ? bf[np][1] : bf[np][0];
                uint32_t b1 = (ni & 1) ? bf[np][3] : bf[np][2];
                MMA16816(acc[mi][ni], ah[mi], b0, b1);
            }
    }

    // epilogue
    #pragma unroll
    for (int mi = 0; mi < 2; mi++) {
        int rA = m0 + wm*32 + mi*16 + (l >> 2);
        int rB = rA + 8;
        float pA0, pA1, pB0, pB1;
        if (MODE == 0) { pA0 = bias[rA]; pA1 = 0.0f; pB0 = bias[rB]; pB1 = 0.0f; }
        else { pA0 = g_alpha[rA]; pA1 = g_beta[rA]; pB0 = g_alpha[rB]; pB1 = g_beta[rB]; }
        #pragma unroll
        for (int ni = 0; ni < 8; ni++) {
            int col = n0 + wn*64 + ni*8 + (l & 3)*2;
            float* c = acc[mi][ni];
            float2 vA, vB;
            if (MODE == 0) {
                vA = make_float2(c[0] + pA0, c[1] + pA0);
                vB = make_float2(c[2] + pB0, c[3] + pB0);
            } else {
                vA = make_float2(gelu_exact(c[0]*pA0 + pA1), gelu_exact(c[1]*pA0 + pA1));
                vB = make_float2(gelu_exact(c[2]*pB0 + pB1), gelu_exact(c[3]*pB0 + pB1));
            }
            *(float2*)(C + (size_t)rA*NP + col) = vA;
            *(float2*)(C + (size_t)rB*NP + col) = vB;
        }
    }
}

// ---------------- attention -------------------------------------------------
__global__ void __launch_bounds__(256) k_logits() {
    int chunk = blockIdx.x, h = blockIdx.y, b = blockIdx.z;
    int tid = threadIdx.x;
    __shared__ float qs[CLSN*DHEAD];
    for (int i = tid; i < CLSN*DHEAD; i += 256) {
        int m = i / DHEAD, d = i - m*DHEAD;
        qs[i] = g_q[(b*CLSN + m)*CDIM + h*DHEAD + d];
    }
    __syncthreads();
    int n = chunk*256 + tid;
    const float* kvp = g_kv + (size_t)b * 2*CDIM*NP + (size_t)(h*DHEAD) * NP + n;
    float acc[CLSN] = {};
    for (int d = 0; d < DHEAD; d++) {
        float kval = kvp[(size_t)d * NP];
        #pragma unroll
        for (int m = 0; m < CLSN; m++) acc[m] += qs[m*DHEAD + d] * kval;
    }
    const float scale = 0.07216878364870322f;
    float* ap = g_attn + (((size_t)(b*NHEADS + h))*CLSN)*NP + n;
    #pragma unroll
    for (int m = 0; m < CLSN; m++) ap[(size_t)m*NP] = acc[m] * scale;
}

__global__ void k_softmax() {
    int row = blockIdx.x, tid = threadIdx.x;
    float* p = g_attn + (size_t)row * NP;
    float v[4];
    #pragma unroll
    for (int i = 0; i < 4; i++) v[i] = p[tid + i*256];
    float mx = fmaxf(fmaxf(v[0],v[1]), fmaxf(v[2],v[3]));
    __shared__ float red[256];
    red[tid] = mx; __syncthreads();
    for (int o = 128; o; o >>= 1) { if (tid < o) red[tid] = fmaxf(red[tid], red[tid+o]); __syncthreads(); }
    mx = red[0]; __syncthreads();
    float s = 0.0f;
    #pragma unroll
    for (int i = 0; i < 4; i++) { v[i] = expf(v[i] - mx); s += v[i]; }
    red[tid] = s; __syncthreads();
    for (int o = 128; o; o >>= 1) { if (tid < o) red[tid] += red[tid+o]; __syncthreads(); }
    float inv = 1.0f / red[0];
    #pragma unroll
    for (int i = 0; i < 4; i++) p[tid + i*256] = v[i] * inv;
}

__global__ void __launch_bounds__(192) k_out() {
    int chunk = blockIdx.x, h = blockIdx.y, b = blockIdx.z;
    int tid = threadIdx.x;
    __shared__ float attn_s[CLSN*256];
    for (int i = tid; i < CLSN*256; i += 192) {
        int m = i >> 8, nn = i & 255;
        attn_s[i] = g_attn[(((size_t)(b*NHEADS + h))*CLSN + m)*NP + chunk*256 + nn];
    }
    __syncthreads();
    const float* vp = g_kv + (size_t)b * 2*CDIM*NP
                    + (size_t)(CDIM + h*DHEAD + tid) * NP + chunk*256;
    float acc[CLSN] = {};
    for (int nn = 0; nn < 256; nn++) {
        float vv = vp[nn];
        #pragma unroll
        for (int m = 0; m < CLSN; m++) acc[m] += attn_s[m*256 + nn] * vv;
    }
    #pragma unroll
    for (int m = 0; m < CLSN; m++)
        atomicAdd(&g_outflat[(b*CLSN + m)*CDIM + h*DHEAD + tid], acc[m]);
}

// ---------------- out_patch = out_cls @ input_patch --------------------------
__global__ void __launch_bounds__(256) k_opatch(const float* __restrict__ patch,
                                                const float* __restrict__ ocls) {
    int chunk = blockIdx.x, b = blockIdx.y;
    int tid = threadIdx.x;
    int n = chunk*256 + tid;
    __shared__ float a_s[CLSN*96];
    float acc[CLSN] = {};
    for (int k0 = 0; k0 < 768; k0 += 96) {
        __syncthreads();
        for (int i = tid; i < CLSN*96; i += 256) {
            int m = i / 96, kk = i - m*96;
            a_s[i] = ocls[(b*CLSN + m)*CDIM + k0 + kk];
        }
        __syncthreads();
        for (int kk = 0; kk < 96; kk++) {
            float pv = patch[(size_t)b*PPB + (size_t)(k0+kk)*NP + n];
            #pragma unroll
            for (int m = 0; m < CLSN; m++) acc[m] += a_s[m*96 + kk] * pv;
        }
    }
    #pragma unroll
    for (int m = 0; m < CLSN; m++) g_opatch[((size_t)b*CLSN + m)*NP + n] = acc[m];
}

// ---------------- im2col transposed + bf16 split -----------------------------
__global__ void k_im2colT() {
    int i = blockIdx.x * 256 + threadIdx.x;       // 16*1024*192
    int b = i / (NP*KPAD);
    int rest = i - b * NP*KPAD;
    int n = rest / KPAD, k = rest - n*KPAD;
    float val = 0.0f;
    if (k < 180) {
        int ic = k / 9, t = k - ic*9;
        int hh = (n >> 5) + t/3 - 1, ww = (n & 31) + t%3 - 1;
        if (hh >= 0 && hh < 32 && ww >= 0 && ww < 32)
            val = g_opatch[((size_t)b*CLSN + ic)*NP + hh*32 + ww];
    }
    __nv_bfloat16 h = __float2bfloat16(val);
    g_ich[i] = h;
    g_icl[i] = __float2bfloat16(val - __bfloat162float(h));
}

// ---------------- launcher ---------------------------------------------------
extern "C" void kernel_launch(void* const* d_in, const int* in_sizes, int n_in,
                              void* d_out, int out_size) {
    const float* x_cls  = (const float*)d_in[0];
    const float* patch  = (const float*)d_in[1];
    const float* ln_w   = (const float*)d_in[2];
    const float* ln_b   = (const float*)d_in[3];
    const float* nx_w   = (const float*)d_in[4];
    const float* nx_b   = (const float*)d_in[5];
    const float* Wq     = (const float*)d_in[6];
    const float* bq     = (const float*)d_in[7];
    const float* Wkv    = (const float*)d_in[8];
    const float* bkv    = (const float*)d_in[9];
    const float* Wp     = (const float*)d_in[10];
    const float* bp     = (const float*)d_in[11];
    const float* Wconv  = (const float*)d_in[12];
    const float* bconv  = (const float*)d_in[13];
    const float* bn_g   = (const float*)d_in[14];
    const float* bn_b   = (const float*)d_in[15];
    const float* bn_m   = (const float*)d_in[16];
    const float* bn_v   = (const float*)d_in[17];
    float* out_cls = (float*)d_out;
    float* y       = out_cls + ROWS*CDIM;

    cudaFuncSetAttribute(gemm_mma<0>, cudaFuncAttributeMaxDynamicSharedMemorySize, SMEMB);
    cudaFuncSetAttribute(gemm_mma<1>, cudaFuncAttributeMaxDynamicSharedMemorySize, SMEMB);

    k_zero<<<(ROWS*CDIM + 255)/256, 256>>>();
    k_lncls<<<ROWS, 256>>>(x_cls, ln_w, ln_b);
    k_psum<<<dim3(48, BATCH), 256>>>(patch);
    k_prep_wkv<<<(2*CDIM*CDIM)/256, 256>>>(Wkv);
    k_nxT<<<dim3(32, 24, BATCH), 256>>>(patch, nx_w, nx_b);
    gemm_nt<0><<<dim3(12, 5), 256>>>(Wq, bq, nullptr, nullptr);
    gemm_mma<0><<<dim3(8, 12, BATCH), 256, SMEMB>>>(bkv, nullptr);
    k_logits<<<dim3(4, NHEADS, BATCH), 256>>>();
    k_softmax<<<BATCH*NHEADS*CLSN, 256>>>();
    k_out<<<dim3(4, NHEADS, BATCH), 192>>>();
    gemm_nt<1><<<dim3(12, 5), 256>>>(Wp, bp, x_cls, out_cls);
    k_prepconv<<<(CDIM*KPAD + 255)/256, 256>>>(Wconv, bconv, bn_g, bn_b, bn_m, bn_v);
    k_opatch<<<dim3(4, BATCH), 256>>>(patch, out_cls);
    k_im2colT<<<(BATCH*NP*KPAD)/256, 256>>>();
    gemm_mma<1><<<dim3(8, 6, BATCH), 256, SMEMB>>>(nullptr, y);
}

// round 5
// speedup vs baseline: 1.7412x; 1.1734x over previous
#include <cuda_runtime.h>
#include <cuda_fp16.h>
#include <cstdint>
#include <math.h>

#define EPSV 1e-5f
#define BATCH 16
#define CLSN 20
#define CDIM 768
#define NHEADS 4
#define DHEAD 192
#define NP 1024
#define ROWS (BATCH*CLSN)
#define PPB (CDIM*NP)
#define KPAD 192

// ---------------- scratch ----------------------------------------------------
__device__ float g_xln[ROWS*CDIM];
__device__ float g_q[ROWS*CDIM];
__device__ float g_sums[32];
__device__ float g_kv[BATCH*2*CDIM*NP];
__device__ float g_attn[BATCH*NHEADS*CLSN*NP];
__device__ float g_outflat[ROWS*CDIM];
__device__ float g_opatch[BATCH*CLSN*NP];
__device__ float g_alpha[CDIM];
__device__ float g_beta[CDIM];
__device__ __align__(128) __half g_Wkvh[2*CDIM*CDIM];
__device__ __align__(128) __half g_Wkvl[2*CDIM*CDIM];
__device__ __align__(128) __half g_nxTh[BATCH*NP*CDIM];   // [b][n][c]
__device__ __align__(128) __half g_W2h[CDIM*KPAD];
__device__ __align__(128) __half g_W2l[CDIM*KPAD];
__device__ __align__(128) __half g_ich[BATCH*NP*KPAD];    // [b][n][k]

__device__ __forceinline__ float gelu_exact(float x) {
    return 0.5f * x * (1.0f + erff(x * 0.70710678118654752440f));
}
__device__ __forceinline__ uint32_t s2u(const void* p) {
    uint32_t a;
    asm("{ .reg .u64 t; cvta.to.shared.u64 t, %1; cvt.u32.u64 %0, t; }" : "=r"(a) : "l"(p));
    return a;
}
__device__ __forceinline__ void cp16(uint32_t dst, const void* src) {
    asm volatile("cp.async.cg.shared.global [%0], [%1], 16;" :: "r"(dst), "l"(src));
}
#define CP_COMMIT() asm volatile("cp.async.commit_group;" ::: "memory")
#define LDSM_X4(r0,r1,r2,r3,a) \
    asm volatile("ldmatrix.sync.aligned.m8n8.x4.shared.b16 {%0,%1,%2,%3}, [%4];" \
                 : "=r"(r0), "=r"(r1), "=r"(r2), "=r"(r3) : "r"(a))
#define MMA16816(c, a, b0, b1) \
    asm volatile("mma.sync.aligned.m16n8k16.row.col.f32.f16.f16.f32 " \
                 "{%0,%1,%2,%3}, {%4,%5,%6,%7}, {%8,%9}, {%0,%1,%2,%3};" \
                 : "+f"((c)[0]), "+f"((c)[1]), "+f"((c)[2]), "+f"((c)[3]) \
                 : "r"((a)[0]), "r"((a)[1]), "r"((a)[2]), "r"((a)[3]), "r"(b0), "r"(b1))

// ---------------- small kernels ---------------------------------------------
__global__ void k_zero() {
    int i = blockIdx.x * 256 + threadIdx.x;
    if (i < ROWS*CDIM) g_outflat[i] = 0.0f;
    if (i < 32) g_sums[i] = 0.0f;
}

__global__ void k_lncls(const float* __restrict__ x, const float* __restrict__ w,
                        const float* __restrict__ bb) {
    int r = blockIdx.x, tid = threadIdx.x;
    const float* xr = x + r * CDIM;
    float v0 = xr[tid], v1 = xr[tid+256], v2 = xr[tid+512];
    __shared__ float red[256];
    __shared__ float s_mu, s_rs;
    red[tid] = v0 + v1 + v2; __syncthreads();
    for (int o = 128; o; o >>= 1) { if (tid < o) red[tid] += red[tid+o]; __syncthreads(); }
    if (tid == 0) s_mu = red[0] * (1.0f/768.0f);
    __syncthreads();
    float mu = s_mu;
    float d0 = v0-mu, d1 = v1-mu, d2 = v2-mu;
    red[tid] = d0*d0 + d1*d1 + d2*d2; __syncthreads();
    for (int o = 128; o; o >>= 1) { if (tid < o) red[tid] += red[tid+o]; __syncthreads(); }
    if (tid == 0) s_rs = rsqrtf(red[0] * (1.0f/768.0f) + EPSV);
    __syncthreads();
    float rs = s_rs;
    float* o = g_xln + r * CDIM;
    o[tid]     = d0*rs*w[tid]     + bb[tid];
    o[tid+256] = d1*rs*w[tid+256] + bb[tid+256];
    o[tid+512] = d2*rs*w[tid+512] + bb[tid+512];
}

__global__ void k_psum(const float* __restrict__ x) {
    int b = blockIdx.y, tid = threadIdx.x;
    const float* p = x + (size_t)b * PPB + blockIdx.x * 16384 + tid;
    float s = 0.0f, q = 0.0f;
    #pragma unroll 8
    for (int i = 0; i < 64; i++) { float v = p[i*256]; s += v; q += v*v; }
    __shared__ float rs[256], rq[256];
    rs[tid] = s; rq[tid] = q; __syncthreads();
    for (int o = 128; o; o >>= 1) {
        if (tid < o) { rs[tid] += rs[tid+o]; rq[tid] += rq[tid+o]; }
        __syncthreads();
    }
    if (tid == 0) { atomicAdd(&g_sums[b], rs[0]); atomicAdd(&g_sums[16+b], rq[0]); }
}

// normalize + transpose + fp16:  g_nxTh[b][n][c]
__global__ void __launch_bounds__(256) k_nxT(const float* __restrict__ x,
                                             const float* __restrict__ w,
                                             const float* __restrict__ bb) {
    __shared__ float t[32][33];
    int b = blockIdx.z, c0 = blockIdx.y*32, n0 = blockIdx.x*32;
    int tx = threadIdx.x & 31, ty = threadIdx.x >> 5;
    float mu  = g_sums[b]    * (1.0f/786432.0f);
    float var = g_sums[16+b] * (1.0f/786432.0f) - mu*mu;
    float rv = rsqrtf(var + EPSV);
    #pragma unroll
    for (int i = 0; i < 4; i++) {
        int c = c0 + ty + i*8;
        float v = x[(size_t)b*PPB + (size_t)c*NP + n0 + tx];
        t[tx][ty + i*8] = (v - mu)*rv*w[c] + bb[c];
    }
    __syncthreads();
    #pragma unroll
    for (int i = 0; i < 4; i++) {
        int n = n0 + ty + i*8;
        float v = t[ty + i*8][tx];
        g_nxTh[((size_t)b*NP + n)*CDIM + c0 + tx] = __float2half_rn(v);
    }
}

__global__ void k_prep_wkv(const float* __restrict__ W) {
    int i = blockIdx.x * 256 + threadIdx.x;
    if (i < 2*CDIM*CDIM) {
        float x = W[i];
        __half h = __float2half_rn(x);
        g_Wkvh[i] = h;
        g_Wkvl[i] = __float2half_rn(x - __half2float(h));
    }
}

__global__ void k_prepconv(const float* __restrict__ Wc, const float* __restrict__ bc,
                           const float* __restrict__ g,  const float* __restrict__ bt,
                           const float* __restrict__ mn, const float* __restrict__ vr) {
    int i = blockIdx.x * 256 + threadIdx.x;
    if (i < CDIM*KPAD) {
        int o = i / KPAD, k = i - o*KPAD;
        float x = (k < 180) ? Wc[o*180 + k] : 0.0f;
        __half h = __float2half_rn(x);
        g_W2h[i] = h;
        g_W2l[i] = __float2half_rn(x - __half2float(h));
    }
    if (i < CDIM) {
        float al = g[i] * rsqrtf(vr[i] + EPSV);
        g_alpha[i] = al;
        g_beta[i]  = (bc[i] - mn[i]) * al + bt[i];
    }
}

// ---------------- small NT GEMM (q proj / out proj) --------------------------
template<int MODE>
__global__ void __launch_bounds__(256) gemm_nt(const float* __restrict__ Bw,
                                               const float* __restrict__ bias,
                                               const float* __restrict__ res,
                                               float* __restrict__ Cext) {
    const float* A = (MODE == 0) ? g_xln : g_outflat;
    float* C = (MODE == 0) ? g_q : Cext;
    __shared__ float As[16*68];
    __shared__ float Bs[16*68];
    int m0 = blockIdx.y * 64, n0 = blockIdx.x * 64;
    int tid = threadIdx.x, tx = tid & 15, ty = tid >> 4;
    float acc[4][4] = {};
    int row = tid >> 2, kq = tid & 3;
    for (int k0 = 0; k0 < 768; k0 += 16) {
        float4 va = *(const float4*)(A  + (m0+row)*768 + k0 + kq*4);
        float4 vb = *(const float4*)(Bw + (n0+row)*768 + k0 + kq*4);
        As[(kq*4+0)*68+row] = va.x; As[(kq*4+1)*68+row] = va.y;
        As[(kq*4+2)*68+row] = va.z; As[(kq*4+3)*68+row] = va.w;
        Bs[(kq*4+0)*68+row] = vb.x; Bs[(kq*4+1)*68+row] = vb.y;
        Bs[(kq*4+2)*68+row] = vb.z; Bs[(kq*4+3)*68+row] = vb.w;
        __syncthreads();
        #pragma unroll
        for (int k = 0; k < 16; k++) {
            float4 a4 = *(const float4*)(&As[k*68 + ty*4]);
            float4 b4 = *(const float4*)(&Bs[k*68 + tx*4]);
            float am[4] = {a4.x, a4.y, a4.z, a4.w};
            float bn[4] = {b4.x, b4.y, b4.z, b4.w};
            #pragma unroll
            for (int i = 0; i < 4; i++)
                #pragma unroll
                for (int j = 0; j < 4; j++) acc[i][j] += am[i]*bn[j];
        }
        __syncthreads();
    }
    #pragma unroll
    for (int i = 0; i < 4; i++) {
        int m = m0 + ty*4 + i;
        #pragma unroll
        for (int j = 0; j < 4; j++) {
            int n = n0 + tx*4 + j;
            float v = acc[i][j] + bias[n];
            if (MODE == 1) v += res[m*768 + n];
            C[m*768 + n] = v;
        }
    }
}

// ---------------- mma.sync fp16-split GEMM, 2-pass ---------------------------
// C[128,128] CTA tile. D = (Ah + Al) * Bh^T, fp32 accum.
// Per k16 slab: 3 tiles (AH, AL, BH). 4-stage cp.async pipeline.
#define TPITCH 48
#define TBYTES (128*TPITCH)          /* 6144 */
#define STAGEB (3*TBYTES)            /* 18432 */
#define NSTG 4
#define SMEMB (NSTG*STAGEB)          /* 73728 */
template<int MODE>
__global__ void __launch_bounds__(256, 2) gemm_mma(const float* __restrict__ bias,
                                                   float* __restrict__ Cout) {
    const int K  = (MODE == 0) ? 768 : KPAD;
    const int NS = K / 16;
    extern __shared__ __align__(1024) char sm[];
    uint32_t sb = s2u(sm);
    int tid = threadIdx.x;
    int w = tid >> 5, l = tid & 31;
    int wm = w >> 1, wn = w & 1;
    int b = blockIdx.z;
    int m0 = blockIdx.y * 128, n0 = blockIdx.x * 128;

    const __half* Ah = (MODE == 0) ? g_Wkvh : g_W2h;
    const __half* Al = (MODE == 0) ? g_Wkvl : g_W2l;
    const __half* Bh = ((MODE == 0) ? g_nxTh : g_ich) + (size_t)b * NP * K;
    float* C = (MODE == 0) ? (g_kv + (size_t)b * 2*CDIM*NP)
                           : (Cout + (size_t)b * CDIM*NP);

    float acc[2][8][4] = {};

    int r = tid >> 1, q = tid & 1;
    uint32_t so = r*TPITCH + q*16;
    size_t arow = (size_t)(m0 + r) * K + q*8;
    size_t brow = (size_t)(n0 + r) * K + q*8;

    auto load_stage = [&](int s) {
        uint32_t st = sb + (s % NSTG) * STAGEB;
        int k0 = s * 16;
        cp16(st + so,            Ah + arow + k0);
        cp16(st + TBYTES + so,   Al + arow + k0);
        cp16(st + 2*TBYTES + so, Bh + brow + k0);
        CP_COMMIT();
    };
    load_stage(0);
    load_stage(1);
    load_stage(2);

    int lrow = (l & 7) + ((l >> 3) & 1) * 8;
    int lko  = (l >> 4) * 16;

    for (int s = 0; s < NS; s++) {
        if (s + 3 <= NS)      asm volatile("cp.async.wait_group 2;" ::: "memory");
        else if (s + 2 == NS) asm volatile("cp.async.wait_group 1;" ::: "memory");
        else                  asm volatile("cp.async.wait_group 0;" ::: "memory");
        __syncthreads();
        if (s + 3 < NS) load_stage(s + 3);
        uint32_t st = sb + (s % NSTG) * STAGEB;
        uint32_t aro = st + (wm*32 + lrow)*TPITCH + lko;
        uint32_t bro = st + 2*TBYTES + (wn*64 + lrow)*TPITCH + lko;
        uint32_t ah[2][4], al[2][4], bf[4][4];
        #pragma unroll
        for (int mi = 0; mi < 2; mi++) {
            LDSM_X4(ah[mi][0], ah[mi][1], ah[mi][2], ah[mi][3], aro + mi*16*TPITCH);
            LDSM_X4(al[mi][0], al[mi][1], al[mi][2], al[mi][3], aro + TBYTES + mi*16*TPITCH);
        }
        #pragma unroll
        for (int np = 0; np < 4; np++)
            LDSM_X4(bf[np][0], bf[np][1], bf[np][2], bf[np][3], bro + np*16*TPITCH);
        #pragma unroll
        for (int mi = 0; mi < 2; mi++)
            #pragma unroll
            for (int ni = 0; ni < 8; ni++) {
                int np = ni >> 1;
                uint32_t b0 = (ni & 1) ? bf[np][1] : bf[np][0];
                uint32_t b1 = (ni & 1) ? bf[np][3] : bf[np][2];
                MMA16816(acc[mi][ni], ah[mi], b0, b1);
                MMA16816(acc[mi][ni], al[mi], b0, b1);
            }
    }

    // epilogue
    #pragma unroll
    for (int mi = 0; mi < 2; mi++) {
        int rA = m0 + wm*32 + mi*16 + (l >> 2);
        int rB = rA + 8;
        float pA0, pA1, pB0, pB1;
        if (MODE == 0) { pA0 = bias[rA]; pA1 = 0.0f; pB0 = bias[rB]; pB1 = 0.0f; }
        else { pA0 = g_alpha[rA]; pA1 = g_beta[rA]; pB0 = g_alpha[rB]; pB1 = g_beta[rB]; }
        #pragma unroll
        for (int ni = 0; ni < 8; ni++) {
            int col = n0 + wn*64 + ni*8 + (l & 3)*2;
            float* c = acc[mi][ni];
            float2 vA, vB;
            if (MODE == 0) {
                vA = make_float2(c[0] + pA0, c[1] + pA0);
                vB = make_float2(c[2] + pB0, c[3] + pB0);
            } else {
                vA = make_float2(gelu_exact(c[0]*pA0 + pA1), gelu_exact(c[1]*pA0 + pA1));
                vB = make_float2(gelu_exact(c[2]*pB0 + pB1), gelu_exact(c[3]*pB0 + pB1));
            }
            *(float2*)(C + (size_t)rA*NP + col) = vA;
            *(float2*)(C + (size_t)rB*NP + col) = vB;
        }
    }
}

// ---------------- attention -------------------------------------------------
__global__ void __launch_bounds__(256) k_logits() {
    int chunk = blockIdx.x, h = blockIdx.y, b = blockIdx.z;
    int tid = threadIdx.x;
    __shared__ float qs[CLSN*DHEAD];
    for (int i = tid; i < CLSN*DHEAD; i += 256) {
        int m = i / DHEAD, d = i - m*DHEAD;
        qs[i] = g_q[(b*CLSN + m)*CDIM + h*DHEAD + d];
    }
    __syncthreads();
    int n = chunk*256 + tid;
    const float* kvp = g_kv + (size_t)b * 2*CDIM*NP + (size_t)(h*DHEAD) * NP + n;
    float acc[CLSN] = {};
    for (int d = 0; d < DHEAD; d++) {
        float kval = kvp[(size_t)d * NP];
        #pragma unroll
        for (int m = 0; m < CLSN; m++) acc[m] += qs[m*DHEAD + d] * kval;
    }
    const float scale = 0.07216878364870322f;
    float* ap = g_attn + (((size_t)(b*NHEADS + h))*CLSN)*NP + n;
    #pragma unroll
    for (int m = 0; m < CLSN; m++) ap[(size_t)m*NP] = acc[m] * scale;
}

__global__ void k_softmax() {
    int row = blockIdx.x, tid = threadIdx.x;
    float* p = g_attn + (size_t)row * NP;
    float v[4];
    #pragma unroll
    for (int i = 0; i < 4; i++) v[i] = p[tid + i*256];
    float mx = fmaxf(fmaxf(v[0],v[1]), fmaxf(v[2],v[3]));
    __shared__ float red[256];
    red[tid] = mx; __syncthreads();
    for (int o = 128; o; o >>= 1) { if (tid < o) red[tid] = fmaxf(red[tid], red[tid+o]); __syncthreads(); }
    mx = red[0]; __syncthreads();
    float s = 0.0f;
    #pragma unroll
    for (int i = 0; i < 4; i++) { v[i] = expf(v[i] - mx); s += v[i]; }
    red[tid] = s; __syncthreads();
    for (int o = 128; o; o >>= 1) { if (tid < o) red[tid] += red[tid+o]; __syncthreads(); }
    float inv = 1.0f / red[0];
    #pragma unroll
    for (int i = 0; i < 4; i++) p[tid + i*256] = v[i] * inv;
}

__global__ void __launch_bounds__(192) k_out() {
    int chunk = blockIdx.x, h = blockIdx.y, b = blockIdx.z;
    int tid = threadIdx.x;
    __shared__ float attn_s[CLSN*256];
    for (int i = tid; i < CLSN*256; i += 192) {
        int m = i >> 8, nn = i & 255;
        attn_s[i] = g_attn[(((size_t)(b*NHEADS + h))*CLSN + m)*NP + chunk*256 + nn];
    }
    __syncthreads();
    const float* vp = g_kv + (size_t)b * 2*CDIM*NP
                    + (size_t)(CDIM + h*DHEAD + tid) * NP + chunk*256;
    float acc[CLSN] = {};
    for (int nn = 0; nn < 256; nn++) {
        float vv = vp[nn];
        #pragma unroll
        for (int m = 0; m < CLSN; m++) acc[m] += attn_s[m*256 + nn] * vv;
    }
    #pragma unroll
    for (int m = 0; m < CLSN; m++)
        atomicAdd(&g_outflat[(b*CLSN + m)*CDIM + h*DHEAD + tid], acc[m]);
}

// ---------------- out_patch = out_cls @ input_patch --------------------------
__global__ void __launch_bounds__(256) k_opatch(const float* __restrict__ patch,
                                                const float* __restrict__ ocls) {
    int chunk = blockIdx.x, b = blockIdx.y;
    int tid = threadIdx.x;
    int n = chunk*256 + tid;
    __shared__ float a_s[CLSN*96];
    float acc[CLSN] = {};
    for (int k0 = 0; k0 < 768; k0 += 96) {
        __syncthreads();
        for (int i = tid; i < CLSN*96; i += 256) {
            int m = i / 96, kk = i - m*96;
            a_s[i] = ocls[(b*CLSN + m)*CDIM + k0 + kk];
        }
        __syncthreads();
        for (int kk = 0; kk < 96; kk++) {
            float pv = patch[(size_t)b*PPB + (size_t)(k0+kk)*NP + n];
            #pragma unroll
            for (int m = 0; m < CLSN; m++) acc[m] += a_s[m*96 + kk] * pv;
        }
    }
    #pragma unroll
    for (int m = 0; m < CLSN; m++) g_opatch[((size_t)b*CLSN + m)*NP + n] = acc[m];
}

// ---------------- im2col transposed + fp16 -----------------------------------
__global__ void k_im2colT() {
    int i = blockIdx.x * 256 + threadIdx.x;
    int b = i / (NP*KPAD);
    int rest = i - b * NP*KPAD;
    int n = rest / KPAD, k = rest - n*KPAD;
    float val = 0.0f;
    if (k < 180) {
        int ic = k / 9, t = k - ic*9;
        int hh = (n >> 5) + t/3 - 1, ww = (n & 31) + t%3 - 1;
        if (hh >= 0 && hh < 32 && ww >= 0 && ww < 32)
            val = g_opatch[((size_t)b*CLSN + ic)*NP + hh*32 + ww];
    }
    g_ich[i] = __float2half_rn(val);
}

// ---------------- launcher ---------------------------------------------------
extern "C" void kernel_launch(void* const* d_in, const int* in_sizes, int n_in,
                              void* d_out, int out_size) {
    const float* x_cls  = (const float*)d_in[0];
    const float* patch  = (const float*)d_in[1];
    const float* ln_w   = (const float*)d_in[2];
    const float* ln_b   = (const float*)d_in[3];
    const float* nx_w   = (const float*)d_in[4];
    const float* nx_b   = (const float*)d_in[5];
    const float* Wq     = (const float*)d_in[6];
    const float* bq     = (const float*)d_in[7];
    const float* Wkv    = (const float*)d_in[8];
    const float* bkv    = (const float*)d_in[9];
    const float* Wp     = (const float*)d_in[10];
    const float* bp     = (const float*)d_in[11];
    const float* Wconv  = (const float*)d_in[12];
    const float* bconv  = (const float*)d_in[13];
    const float* bn_g   = (const float*)d_in[14];
    const float* bn_b   = (const float*)d_in[15];
    const float* bn_m   = (const float*)d_in[16];
    const float* bn_v   = (const float*)d_in[17];
    float* out_cls = (float*)d_out;
    float* y       = out_cls + ROWS*CDIM;

    cudaFuncSetAttribute(gemm_mma<0>, cudaFuncAttributeMaxDynamicSharedMemorySize, SMEMB);
    cudaFuncSetAttribute(gemm_mma<1>, cudaFuncAttributeMaxDynamicSharedMemorySize, SMEMB);

    k_zero<<<(ROWS*CDIM + 255)/256, 256>>>();
    k_lncls<<<ROWS, 256>>>(x_cls, ln_w, ln_b);
    k_psum<<<dim3(48, BATCH), 256>>>(patch);
    k_prep_wkv<<<(2*CDIM*CDIM)/256, 256>>>(Wkv);
    k_nxT<<<dim3(32, 24, BATCH), 256>>>(patch, nx_w, nx_b);
    gemm_nt<0><<<dim3(12, 5), 256>>>(Wq, bq, nullptr, nullptr);
    gemm_mma<0><<<dim3(8, 12, BATCH), 256, SMEMB>>>(bkv, nullptr);
    k_logits<<<dim3(4, NHEADS, BATCH), 256>>>();
    k_softmax<<<BATCH*NHEADS*CLSN, 256>>>();
    k_out<<<dim3(4, NHEADS, BATCH), 192>>>();
    gemm_nt<1><<<dim3(12, 5), 256>>>(Wp, bp, x_cls, out_cls);
    k_prepconv<<<(CDIM*KPAD + 255)/256, 256>>>(Wconv, bconv, bn_g, bn_b, bn_m, bn_v);
    k_opatch<<<dim3(4, BATCH), 256>>>(patch, out_cls);
    k_im2colT<<<(BATCH*NP*KPAD)/256, 256>>>();
    gemm_mma<1><<<dim3(8, 6, BATCH), 256, SMEMB>>>(nullptr, y);
}

// round 6
// speedup vs baseline: 2.1642x; 1.2429x over previous
#include <cuda_runtime.h>
#include <cuda_fp16.h>
#include <cstdint>
#include <math.h>

#define EPSV 1e-5f
#define BATCH 16
#define CLSN 20
#define CDIM 768
#define NHEADS 4
#define DHEAD 192
#define NP 1024
#define ROWS (BATCH*CLSN)
#define PPB (CDIM*NP)
#define KPAD 192

// ---------------- scratch ----------------------------------------------------
__device__ float g_xln[ROWS*CDIM];
__device__ float g_q[ROWS*CDIM];
__device__ float g_sums[32];
__device__ float g_kv[BATCH*2*CDIM*NP];
__device__ float g_attn[BATCH*NHEADS*CLSN*NP];
__device__ float g_outflat[ROWS*CDIM];
__device__ float g_opatch[BATCH*CLSN*NP];
__device__ float g_alpha[CDIM];
__device__ float g_beta[CDIM];
__device__ __align__(128) __half g_Wkvh[2*CDIM*CDIM];
__device__ __align__(128) __half g_nxTh[BATCH*NP*CDIM];   // [b][n][c]
__device__ __align__(128) __half g_W2h[CDIM*KPAD];
__device__ __align__(128) __half g_ich[BATCH*NP*KPAD];    // [b][n][k]

__device__ __forceinline__ float gelu_exact(float x) {
    return 0.5f * x * (1.0f + erff(x * 0.70710678118654752440f));
}
__device__ __forceinline__ uint32_t s2u(const void* p) {
    uint32_t a;
    asm("{ .reg .u64 t; cvta.to.shared.u64 t, %1; cvt.u32.u64 %0, t; }" : "=r"(a) : "l"(p));
    return a;
}
__device__ __forceinline__ void cp16(uint32_t dst, const void* src) {
    asm volatile("cp.async.cg.shared.global [%0], [%1], 16;" :: "r"(dst), "l"(src));
}
#define CP_COMMIT() asm volatile("cp.async.commit_group;" ::: "memory")
#define LDSM_X4(r0,r1,r2,r3,a) \
    asm volatile("ldmatrix.sync.aligned.m8n8.x4.shared.b16 {%0,%1,%2,%3}, [%4];" \
                 : "=r"(r0), "=r"(r1), "=r"(r2), "=r"(r3) : "r"(a))
#define MMA16816(c, a, b0, b1) \
    asm volatile("mma.sync.aligned.m16n8k16.row.col.f32.f16.f16.f32 " \
                 "{%0,%1,%2,%3}, {%4,%5,%6,%7}, {%8,%9}, {%0,%1,%2,%3};" \
                 : "+f"((c)[0]), "+f"((c)[1]), "+f"((c)[2]), "+f"((c)[3]) \
                 : "r"((a)[0]), "r"((a)[1]), "r"((a)[2]), "r"((a)[3]), "r"(b0), "r"(b1))

// ---------------- small kernels ---------------------------------------------
__global__ void k_zero() {
    int i = blockIdx.x * 256 + threadIdx.x;
    if (i < ROWS*CDIM) g_outflat[i] = 0.0f;
    if (i < 32) g_sums[i] = 0.0f;
}

__global__ void k_lncls(const float* __restrict__ x, const float* __restrict__ w,
                        const float* __restrict__ bb) {
    int r = blockIdx.x, tid = threadIdx.x;
    const float* xr = x + r * CDIM;
    float v0 = xr[tid], v1 = xr[tid+256], v2 = xr[tid+512];
    __shared__ float red[256];
    __shared__ float s_mu, s_rs;
    red[tid] = v0 + v1 + v2; __syncthreads();
    for (int o = 128; o; o >>= 1) { if (tid < o) red[tid] += red[tid+o]; __syncthreads(); }
    if (tid == 0) s_mu = red[0] * (1.0f/768.0f);
    __syncthreads();
    float mu = s_mu;
    float d0 = v0-mu, d1 = v1-mu, d2 = v2-mu;
    red[tid] = d0*d0 + d1*d1 + d2*d2; __syncthreads();
    for (int o = 128; o; o >>= 1) { if (tid < o) red[tid] += red[tid+o]; __syncthreads(); }
    if (tid == 0) s_rs = rsqrtf(red[0] * (1.0f/768.0f) + EPSV);
    __syncthreads();
    float rs = s_rs;
    float* o = g_xln + r * CDIM;
    o[tid]     = d0*rs*w[tid]     + bb[tid];
    o[tid+256] = d1*rs*w[tid+256] + bb[tid+256];
    o[tid+512] = d2*rs*w[tid+512] + bb[tid+512];
}

__global__ void k_psum(const float* __restrict__ x) {
    int b = blockIdx.y, tid = threadIdx.x;
    const float* p = x + (size_t)b * PPB + blockIdx.x * 16384 + tid;
    float s = 0.0f, q = 0.0f;
    #pragma unroll 8
    for (int i = 0; i < 64; i++) { float v = p[i*256]; s += v; q += v*v; }
    __shared__ float rs[256], rq[256];
    rs[tid] = s; rq[tid] = q; __syncthreads();
    for (int o = 128; o; o >>= 1) {
        if (tid < o) { rs[tid] += rs[tid+o]; rq[tid] += rq[tid+o]; }
        __syncthreads();
    }
    if (tid == 0) { atomicAdd(&g_sums[b], rs[0]); atomicAdd(&g_sums[16+b], rq[0]); }
}

// normalize + transpose + fp16:  g_nxTh[b][n][c]
__global__ void __launch_bounds__(256) k_nxT(const float* __restrict__ x,
                                             const float* __restrict__ w,
                                             const float* __restrict__ bb) {
    __shared__ float t[32][33];
    int b = blockIdx.z, c0 = blockIdx.y*32, n0 = blockIdx.x*32;
    int tx = threadIdx.x & 31, ty = threadIdx.x >> 5;
    float mu  = g_sums[b]    * (1.0f/786432.0f);
    float var = g_sums[16+b] * (1.0f/786432.0f) - mu*mu;
    float rv = rsqrtf(var + EPSV);
    #pragma unroll
    for (int i = 0; i < 4; i++) {
        int c = c0 + ty + i*8;
        float v = x[(size_t)b*PPB + (size_t)c*NP + n0 + tx];
        t[tx][ty + i*8] = (v - mu)*rv*w[c] + bb[c];
    }
    __syncthreads();
    #pragma unroll
    for (int i = 0; i < 4; i++) {
        int n = n0 + ty + i*8;
        float v = t[ty + i*8][tx];
        g_nxTh[((size_t)b*NP + n)*CDIM + c0 + tx] = __float2half_rn(v);
    }
}

__global__ void k_prep_wkv(const float* __restrict__ W) {
    int i = blockIdx.x * 256 + threadIdx.x;
    if (i < 2*CDIM*CDIM) g_Wkvh[i] = __float2half_rn(W[i]);
}

__global__ void k_prepconv(const float* __restrict__ Wc, const float* __restrict__ bc,
                           const float* __restrict__ g,  const float* __restrict__ bt,
                           const float* __restrict__ mn, const float* __restrict__ vr) {
    int i = blockIdx.x * 256 + threadIdx.x;
    if (i < CDIM*KPAD) {
        int o = i / KPAD, k = i - o*KPAD;
        g_W2h[i] = __float2half_rn((k < 180) ? Wc[o*180 + k] : 0.0f);
    }
    if (i < CDIM) {
        float al = g[i] * rsqrtf(vr[i] + EPSV);
        g_alpha[i] = al;
        g_beta[i]  = (bc[i] - mn[i]) * al + bt[i];
    }
}

// ---------------- small NT GEMM (q proj / out proj) --------------------------
template<int MODE>
__global__ void __launch_bounds__(256) gemm_nt(const float* __restrict__ Bw,
                                               const float* __restrict__ bias,
                                               const float* __restrict__ res,
                                               float* __restrict__ Cext) {
    const float* A = (MODE == 0) ? g_xln : g_outflat;
    float* C = (MODE == 0) ? g_q : Cext;
    __shared__ float As[16*68];
    __shared__ float Bs[16*68];
    int m0 = blockIdx.y * 64, n0 = blockIdx.x * 64;
    int tid = threadIdx.x, tx = tid & 15, ty = tid >> 4;
    float acc[4][4] = {};
    int row = tid >> 2, kq = tid & 3;
    for (int k0 = 0; k0 < 768; k0 += 16) {
        float4 va = *(const float4*)(A  + (m0+row)*768 + k0 + kq*4);
        float4 vb = *(const float4*)(Bw + (n0+row)*768 + k0 + kq*4);
        As[(kq*4+0)*68+row] = va.x; As[(kq*4+1)*68+row] = va.y;
        As[(kq*4+2)*68+row] = va.z; As[(kq*4+3)*68+row] = va.w;
        Bs[(kq*4+0)*68+row] = vb.x; Bs[(kq*4+1)*68+row] = vb.y;
        Bs[(kq*4+2)*68+row] = vb.z; Bs[(kq*4+3)*68+row] = vb.w;
        __syncthreads();
        #pragma unroll
        for (int k = 0; k < 16; k++) {
            float4 a4 = *(const float4*)(&As[k*68 + ty*4]);
            float4 b4 = *(const float4*)(&Bs[k*68 + tx*4]);
            float am[4] = {a4.x, a4.y, a4.z, a4.w};
            float bn[4] = {b4.x, b4.y, b4.z, b4.w};
            #pragma unroll
            for (int i = 0; i < 4; i++)
                #pragma unroll
                for (int j = 0; j < 4; j++) acc[i][j] += am[i]*bn[j];
        }
        __syncthreads();
    }
    #pragma unroll
    for (int i = 0; i < 4; i++) {
        int m = m0 + ty*4 + i;
        #pragma unroll
        for (int j = 0; j < 4; j++) {
            int n = n0 + tx*4 + j;
            float v = acc[i][j] + bias[n];
            if (MODE == 1) v += res[m*768 + n];
            C[m*768 + n] = v;
        }
    }
}

// ---------------- mma.sync fp16 GEMM, single-pass ----------------------------
// C[128,128] CTA tile. D = Ah * Bh^T, fp32 accum.
// Per k16 slab: 2 tiles (AH, BH). 4-stage cp.async pipeline.
#define TPITCH 48
#define TBYTES (128*TPITCH)          /* 6144 */
#define STAGEB (2*TBYTES)            /* 12288 */
#define NSTG 4
#define SMEMB (NSTG*STAGEB)          /* 49152 */
template<int MODE>
__global__ void __launch_bounds__(256, 2) gemm_mma(const float* __restrict__ bias,
                                                   float* __restrict__ Cout) {
    const int K  = (MODE == 0) ? 768 : KPAD;
    const int NS = K / 16;
    extern __shared__ __align__(1024) char sm[];
    uint32_t sb = s2u(sm);
    int tid = threadIdx.x;
    int w = tid >> 5, l = tid & 31;
    int wm = w >> 1, wn = w & 1;
    int b = blockIdx.z;
    int m0 = blockIdx.y * 128, n0 = blockIdx.x * 128;

    const __half* Ah = (MODE == 0) ? g_Wkvh : g_W2h;
    const __half* Bh = ((MODE == 0) ? g_nxTh : g_ich) + (size_t)b * NP * K;
    float* C = (MODE == 0) ? (g_kv + (size_t)b * 2*CDIM*NP)
                           : (Cout + (size_t)b * CDIM*NP);

    float acc[2][8][4] = {};

    int r = tid >> 1, q = tid & 1;
    uint32_t so = r*TPITCH + q*16;
    size_t arow = (size_t)(m0 + r) * K + q*8;
    size_t brow = (size_t)(n0 + r) * K + q*8;

    auto load_stage = [&](int s) {
        uint32_t st = sb + (s % NSTG) * STAGEB;
        int k0 = s * 16;
        cp16(st + so,          Ah + arow + k0);
        cp16(st + TBYTES + so, Bh + brow + k0);
        CP_COMMIT();
    };
    load_stage(0);
    load_stage(1);
    load_stage(2);

    int lrow = (l & 7) + ((l >> 3) & 1) * 8;
    int lko  = (l >> 4) * 16;

    for (int s = 0; s < NS; s++) {
        if (s + 3 <= NS)      asm volatile("cp.async.wait_group 2;" ::: "memory");
        else if (s + 2 == NS) asm volatile("cp.async.wait_group 1;" ::: "memory");
        else                  asm volatile("cp.async.wait_group 0;" ::: "memory");
        __syncthreads();
        if (s + 3 < NS) load_stage(s + 3);
        uint32_t st = sb + (s % NSTG) * STAGEB;
        uint32_t aro = st + (wm*32 + lrow)*TPITCH + lko;
        uint32_t bro = st + TBYTES + (wn*64 + lrow)*TPITCH + lko;
        uint32_t ah[2][4], bf[4][4];
        #pragma unroll
        for (int mi = 0; mi < 2; mi++)
            LDSM_X4(ah[mi][0], ah[mi][1], ah[mi][2], ah[mi][3], aro + mi*16*TPITCH);
        #pragma unroll
        for (int np = 0; np < 4; np++)
            LDSM_X4(bf[np][0], bf[np][1], bf[np][2], bf[np][3], bro + np*16*TPITCH);
        #pragma unroll
        for (int mi = 0; mi < 2; mi++)
            #pragma unroll
            for (int ni = 0; ni < 8; ni++) {
                int np = ni >> 1;
                uint32_t b0 = (ni & 1) ? bf[np][1] : bf[np][0];
                uint32_t b1 = (ni & 1) ? bf[np][3] : bf[np][2];
                MMA16816(acc[mi][ni], ah[mi], b0, b1);
            }
    }

    // epilogue
    #pragma unroll
    for (int mi = 0; mi < 2; mi++) {
        int rA = m0 + wm*32 + mi*16 + (l >> 2);
        int rB = rA + 8;
        float pA0, pA1, pB0, pB1;
        if (MODE == 0) { pA0 = bias[rA]; pA1 = 0.0f; pB0 = bias[rB]; pB1 = 0.0f; }
        else { pA0 = g_alpha[rA]; pA1 = g_beta[rA]; pB0 = g_alpha[rB]; pB1 = g_beta[rB]; }
        #pragma unroll
        for (int ni = 0; ni < 8; ni++) {
            int col = n0 + wn*64 + ni*8 + (l & 3)*2;
            float* c = acc[mi][ni];
            float2 vA, vB;
            if (MODE == 0) {
                vA = make_float2(c[0] + pA0, c[1] + pA0);
                vB = make_float2(c[2] + pB0, c[3] + pB0);
            } else {
                vA = make_float2(gelu_exact(c[0]*pA0 + pA1), gelu_exact(c[1]*pA0 + pA1));
                vB = make_float2(gelu_exact(c[2]*pB0 + pB1), gelu_exact(c[3]*pB0 + pB1));
            }
            *(float2*)(C + (size_t)rA*NP + col) = vA;
            *(float2*)(C + (size_t)rB*NP + col) = vB;
        }
    }
}

// ---------------- attention -------------------------------------------------
__global__ void __launch_bounds__(256) k_logits() {
    int chunk = blockIdx.x, h = blockIdx.y, b = blockIdx.z;
    int tid = threadIdx.x;
    __shared__ float qs[CLSN*DHEAD];
    for (int i = tid; i < CLSN*DHEAD; i += 256) {
        int m = i / DHEAD, d = i - m*DHEAD;
        qs[i] = g_q[(b*CLSN + m)*CDIM + h*DHEAD + d];
    }
    __syncthreads();
    int n = chunk*256 + tid;
    const float* kvp = g_kv + (size_t)b * 2*CDIM*NP + (size_t)(h*DHEAD) * NP + n;
    float acc[CLSN] = {};
    for (int d = 0; d < DHEAD; d++) {
        float kval = kvp[(size_t)d * NP];
        #pragma unroll
        for (int m = 0; m < CLSN; m++) acc[m] += qs[m*DHEAD + d] * kval;
    }
    const float scale = 0.07216878364870322f;
    float* ap = g_attn + (((size_t)(b*NHEADS + h))*CLSN)*NP + n;
    #pragma unroll
    for (int m = 0; m < CLSN; m++) ap[(size_t)m*NP] = acc[m] * scale;
}

__global__ void k_softmax() {
    int row = blockIdx.x, tid = threadIdx.x;
    float* p = g_attn + (size_t)row * NP;
    float v[4];
    #pragma unroll
    for (int i = 0; i < 4; i++) v[i] = p[tid + i*256];
    float mx = fmaxf(fmaxf(v[0],v[1]), fmaxf(v[2],v[3]));
    __shared__ float red[256];
    red[tid] = mx; __syncthreads();
    for (int o = 128; o; o >>= 1) { if (tid < o) red[tid] = fmaxf(red[tid], red[tid+o]); __syncthreads(); }
    mx = red[0]; __syncthreads();
    float s = 0.0f;
    #pragma unroll
    for (int i = 0; i < 4; i++) { v[i] = expf(v[i] - mx); s += v[i]; }
    red[tid] = s; __syncthreads();
    for (int o = 128; o; o >>= 1) { if (tid < o) red[tid] += red[tid+o]; __syncthreads(); }
    float inv = 1.0f / red[0];
    #pragma unroll
    for (int i = 0; i < 4; i++) p[tid + i*256] = v[i] * inv;
}

__global__ void __launch_bounds__(192) k_out() {
    int chunk = blockIdx.x, h = blockIdx.y, b = blockIdx.z;
    int tid = threadIdx.x;
    __shared__ float attn_s[CLSN*256];
    for (int i = tid; i < CLSN*256; i += 192) {
        int m = i >> 8, nn = i & 255;
        attn_s[i] = g_attn[(((size_t)(b*NHEADS + h))*CLSN + m)*NP + chunk*256 + nn];
    }
    __syncthreads();
    const float* vp = g_kv + (size_t)b * 2*CDIM*NP
                    + (size_t)(CDIM + h*DHEAD + tid) * NP + chunk*256;
    float acc[CLSN] = {};
    for (int nn = 0; nn < 256; nn++) {
        float vv = vp[nn];
        #pragma unroll
        for (int m = 0; m < CLSN; m++) acc[m] += attn_s[m*256 + nn] * vv;
    }
    #pragma unroll
    for (int m = 0; m < CLSN; m++)
        atomicAdd(&g_outflat[(b*CLSN + m)*CDIM + h*DHEAD + tid], acc[m]);
}

// ---------------- out_patch = out_cls @ input_patch --------------------------
__global__ void __launch_bounds__(256) k_opatch(const float* __restrict__ patch,
                                                const float* __restrict__ ocls) {
    int chunk = blockIdx.x, b = blockIdx.y;
    int tid = threadIdx.x;
    int n = chunk*256 + tid;
    __shared__ float a_s[CLSN*96];
    float acc[CLSN] = {};
    for (int k0 = 0; k0 < 768; k0 += 96) {
        __syncthreads();
        for (int i = tid; i < CLSN*96; i += 256) {
            int m = i / 96, kk = i - m*96;
            a_s[i] = ocls[(b*CLSN + m)*CDIM + k0 + kk];
        }
        __syncthreads();
        for (int kk = 0; kk < 96; kk++) {
            float pv = patch[(size_t)b*PPB + (size_t)(k0+kk)*NP + n];
            #pragma unroll
            for (int m = 0; m < CLSN; m++) acc[m] += a_s[m*96 + kk] * pv;
        }
    }
    #pragma unroll
    for (int m = 0; m < CLSN; m++) g_opatch[((size_t)b*CLSN + m)*NP + n] = acc[m];
}

// ---------------- im2col transposed + fp16 -----------------------------------
__global__ void k_im2colT() {
    int i = blockIdx.x * 256 + threadIdx.x;
    int b = i / (NP*KPAD);
    int rest = i - b * NP*KPAD;
    int n = rest / KPAD, k = rest - n*KPAD;
    float val = 0.0f;
    if (k < 180) {
        int ic = k / 9, t = k - ic*9;
        int hh = (n >> 5) + t/3 - 1, ww = (n & 31) + t%3 - 1;
        if (hh >= 0 && hh < 32 && ww >= 0 && ww < 32)
            val = g_opatch[((size_t)b*CLSN + ic)*NP + hh*32 + ww];
    }
    g_ich[i] = __float2half_rn(val);
}

// ---------------- launcher ---------------------------------------------------
extern "C" void kernel_launch(void* const* d_in, const int* in_sizes, int n_in,
                              void* d_out, int out_size) {
    const float* x_cls  = (const float*)d_in[0];
    const float* patch  = (const float*)d_in[1];
    const float* ln_w   = (const float*)d_in[2];
    const float* ln_b   = (const float*)d_in[3];
    const float* nx_w   = (const float*)d_in[4];
    const float* nx_b   = (const float*)d_in[5];
    const float* Wq     = (const float*)d_in[6];
    const float* bq     = (const float*)d_in[7];
    const float* Wkv    = (const float*)d_in[8];
    const float* bkv    = (const float*)d_in[9];
    const float* Wp     = (const float*)d_in[10];
    const float* bp     = (const float*)d_in[11];
    const float* Wconv  = (const float*)d_in[12];
    const float* bconv  = (const float*)d_in[13];
    const float* bn_g   = (const float*)d_in[14];
    const float* bn_b   = (const float*)d_in[15];
    const float* bn_m   = (const float*)d_in[16];
    const float* bn_v   = (const float*)d_in[17];
    float* out_cls = (float*)d_out;
    float* y       = out_cls + ROWS*CDIM;

    cudaFuncSetAttribute(gemm_mma<0>, cudaFuncAttributeMaxDynamicSharedMemorySize, SMEMB);
    cudaFuncSetAttribute(gemm_mma<1>, cudaFuncAttributeMaxDynamicSharedMemorySize, SMEMB);

    k_zero<<<(ROWS*CDIM + 255)/256, 256>>>();
    k_lncls<<<ROWS, 256>>>(x_cls, ln_w, ln_b);
    k_psum<<<dim3(48, BATCH), 256>>>(patch);
    k_prep_wkv<<<(2*CDIM*CDIM)/256, 256>>>(Wkv);
    k_nxT<<<dim3(32, 24, BATCH), 256>>>(patch, nx_w, nx_b);
    gemm_nt<0><<<dim3(12, 5), 256>>>(Wq, bq, nullptr, nullptr);
    gemm_mma<0><<<dim3(8, 12, BATCH), 256, SMEMB>>>(bkv, nullptr);
    k_logits<<<dim3(4, NHEADS, BATCH), 256>>>();
    k_softmax<<<BATCH*NHEADS*CLSN, 256>>>();
    k_out<<<dim3(4, NHEADS, BATCH), 192>>>();
    gemm_nt<1><<<dim3(12, 5), 256>>>(Wp, bp, x_cls, out_cls);
    k_prepconv<<<(CDIM*KPAD + 255)/256, 256>>>(Wconv, bconv, bn_g, bn_b, bn_m, bn_v);
    k_opatch<<<dim3(4, BATCH), 256>>>(patch, out_cls);
    k_im2colT<<<(BATCH*NP*KPAD)/256, 256>>>();
    gemm_mma<1><<<dim3(8, 6, BATCH), 256, SMEMB>>>(nullptr, y);
}